// round 12
// baseline (speedup 1.0000x reference)
#include <cuda_runtime.h>
#include <math.h>

#define NU 100000
#define NI 50000
#define NT 10000
#define NNODES 160000
#define NE 800000
#define DD 64
#define EPS 192   // EP record stride: [eh 64 | px 64 | off 64]

typedef unsigned long long u64;

// ---------------- device scratch ----------------
__device__ float g_embsB[NNODES * DD];
__device__ float g_offB[NNODES * DD];
__device__ float g_EP[NNODES * EPS];

__device__ int g_deg[NNODES];
__device__ int g_scan[NNODES];
__device__ int g_csr_off[NNODES + 1];
__device__ int g_pos[NNODES];
__device__ int g_csr_tail[NE];
__device__ int g_bsums[256];

// ---------------- packed f32x2 helpers ----------------
__device__ __forceinline__ u64 pack2(float a, float b) {
    u64 r; asm("mov.b64 %0,{%1,%2};" : "=l"(r) : "f"(a), "f"(b)); return r;
}
__device__ __forceinline__ u64 dup2(float a) {
    u64 r; asm("mov.b64 %0,{%1,%1};" : "=l"(r) : "f"(a)); return r;
}
__device__ __forceinline__ float2 unpack2(u64 v) {
    float2 f; asm("mov.b64 {%0,%1},%2;" : "=f"(f.x), "=f"(f.y) : "l"(v)); return f;
}
__device__ __forceinline__ u64 ffma2(u64 a, u64 b, u64 c) {
    u64 d; asm("fma.rn.f32x2 %0,%1,%2,%3;" : "=l"(d) : "l"(a), "l"(b), "l"(c)); return d;
}

// ---------------- CSR build (multi-kernel, proven fastest) ----------------
__global__ void zero_deg_kernel() {
    int i = blockIdx.x * blockDim.x + threadIdx.x;
    if (i < NNODES) g_deg[i] = 0;
}

__global__ void hist_kernel(const int* __restrict__ head) {
    int e = blockIdx.x * blockDim.x + threadIdx.x;
    if (e < NE) atomicAdd(&g_deg[head[e]], 1);
}

#define SCAN_B 1024
__global__ void scan_block_kernel() {
    __shared__ int sh[SCAN_B];
    int g = blockIdx.x * SCAN_B + threadIdx.x;
    int v = (g < NNODES) ? g_deg[g] : 0;
    sh[threadIdx.x] = v;
    __syncthreads();
    for (int of = 1; of < SCAN_B; of <<= 1) {
        int t = (threadIdx.x >= of) ? sh[threadIdx.x - of] : 0;
        __syncthreads();
        sh[threadIdx.x] += t;
        __syncthreads();
    }
    if (g < NNODES) g_scan[g] = sh[threadIdx.x];
    if (threadIdx.x == SCAN_B - 1) g_bsums[blockIdx.x] = sh[threadIdx.x];
}

__global__ void scan_sums_kernel(int nb) {
    __shared__ int sh[256];
    int v = (threadIdx.x < nb) ? g_bsums[threadIdx.x] : 0;
    sh[threadIdx.x] = v;
    __syncthreads();
    for (int of = 1; of < 256; of <<= 1) {
        int t = (threadIdx.x >= of) ? sh[threadIdx.x - of] : 0;
        __syncthreads();
        sh[threadIdx.x] += t;
        __syncthreads();
    }
    if (threadIdx.x < nb) g_bsums[threadIdx.x] = sh[threadIdx.x] - v;
    if (threadIdx.x == 0) g_csr_off[0] = 0;
}

__global__ void scan_add_kernel() {
    int g = blockIdx.x * SCAN_B + threadIdx.x;
    if (g < NNODES) {
        int inc = g_scan[g] + g_bsums[blockIdx.x];
        g_csr_off[g + 1] = inc;
        g_pos[g] = inc - g_deg[g];
    }
}

__global__ void scatter_kernel(const int* __restrict__ head, const int* __restrict__ tail) {
    int e = blockIdx.x * blockDim.x + threadIdx.x;
    if (e < NE) {
        int h = head[e];
        int p = atomicAdd(&g_pos[h], 1);
        g_csr_tail[p] = tail[e];
    }
}

// ---------------- MLP (R10 shape): 128 thr, tile 128x64, thread 8x8 ----------------
__device__ __forceinline__ int xswz(int k, int r) {
    return k * 128 + (r ^ ((k >> 3 & 3) << 3));
}
__device__ __forceinline__ int wpos(int k, int j) {
    int m = j >> 2;
    return k * 64 + ((m & 1) << 5) + ((m >> 1) << 2) + (j & 3);
}

template <int LAYER>
__global__ __launch_bounds__(128) void mlp_kernel(
    const float* __restrict__ ue, const float* __restrict__ ie, const float* __restrict__ te,
    const float* __restrict__ uo, const float* __restrict__ io, const float* __restrict__ to,
    const float* __restrict__ W1, const float* __restrict__ b1,
    const float* __restrict__ W2, const float* __restrict__ b2) {
    __shared__ __align__(16) float Ws[64 * 64];    // 16 KB
    __shared__ __align__(16) float Xs[64 * 128];   // 32 KB

    const int tid = threadIdx.x;
    const int row0 = blockIdx.x * 128;

    for (int i = tid; i < 4096; i += 128) {
        int j = i >> 6, k = i & 63;
        Ws[wpos(k, j)] = W1[i];
    }
    for (int i = tid; i < 2048; i += 128) {
        int rl = i >> 4, c4 = (i & 15) * 4;
        int row = row0 + rl;
        const float* src;
        if (LAYER == 0) {
            if (row < NU) src = ue + (size_t)row * 64;
            else if (row < NU + NI) src = ie + (size_t)(row - NU) * 64;
            else src = te + (size_t)(row - NU - NI) * 64;
        } else {
            src = g_embsB + (size_t)row * 64;
        }
        float4 v = *(const float4*)(src + c4);
        Xs[xswz(c4 + 0, rl)] = v.x;
        Xs[xswz(c4 + 1, rl)] = v.y;
        Xs[xswz(c4 + 2, rl)] = v.z;
        Xs[xswz(c4 + 3, rl)] = v.w;
    }
    __syncthreads();

    const int tx = tid & 7, ty = tid >> 3;
    const int j0 = tx * 8, r0 = ty * 8;

    u64 acc[4][8];
    {
        float4 ba = *(const float4*)(b1 + j0);
        float4 bb = *(const float4*)(b1 + j0 + 4);
        u64 d0 = dup2(ba.x), d1 = dup2(ba.y), d2 = dup2(ba.z), d3 = dup2(ba.w);
        u64 d4 = dup2(bb.x), d5 = dup2(bb.y), d6 = dup2(bb.z), d7 = dup2(bb.w);
#pragma unroll
        for (int i = 0; i < 4; i++) {
            acc[i][0] = d0; acc[i][1] = d1; acc[i][2] = d2; acc[i][3] = d3;
            acc[i][4] = d4; acc[i][5] = d5; acc[i][6] = d6; acc[i][7] = d7;
        }
    }

#pragma unroll 8
    for (int k = 0; k < 64; k++) {
        int xb = k * 128 + (r0 ^ ((k >> 3 & 3) << 3));
        ulonglong2 xA = *(const ulonglong2*)&Xs[xb];
        ulonglong2 xB = *(const ulonglong2*)&Xs[xb + 4];
        float4 wa = *(const float4*)&Ws[k * 64 + tx * 4];
        float4 wb = *(const float4*)&Ws[k * 64 + 32 + tx * 4];
        u64 w0 = dup2(wa.x), w1 = dup2(wa.y), w2 = dup2(wa.z), w3 = dup2(wa.w);
        u64 w4 = dup2(wb.x), w5 = dup2(wb.y), w6 = dup2(wb.z), w7 = dup2(wb.w);
        acc[0][0] = ffma2(xA.x, w0, acc[0][0]); acc[0][1] = ffma2(xA.x, w1, acc[0][1]);
        acc[0][2] = ffma2(xA.x, w2, acc[0][2]); acc[0][3] = ffma2(xA.x, w3, acc[0][3]);
        acc[0][4] = ffma2(xA.x, w4, acc[0][4]); acc[0][5] = ffma2(xA.x, w5, acc[0][5]);
        acc[0][6] = ffma2(xA.x, w6, acc[0][6]); acc[0][7] = ffma2(xA.x, w7, acc[0][7]);
        acc[1][0] = ffma2(xA.y, w0, acc[1][0]); acc[1][1] = ffma2(xA.y, w1, acc[1][1]);
        acc[1][2] = ffma2(xA.y, w2, acc[1][2]); acc[1][3] = ffma2(xA.y, w3, acc[1][3]);
        acc[1][4] = ffma2(xA.y, w4, acc[1][4]); acc[1][5] = ffma2(xA.y, w5, acc[1][5]);
        acc[1][6] = ffma2(xA.y, w6, acc[1][6]); acc[1][7] = ffma2(xA.y, w7, acc[1][7]);
        acc[2][0] = ffma2(xB.x, w0, acc[2][0]); acc[2][1] = ffma2(xB.x, w1, acc[2][1]);
        acc[2][2] = ffma2(xB.x, w2, acc[2][2]); acc[2][3] = ffma2(xB.x, w3, acc[2][3]);
        acc[2][4] = ffma2(xB.x, w4, acc[2][4]); acc[2][5] = ffma2(xB.x, w5, acc[2][5]);
        acc[2][6] = ffma2(xB.x, w6, acc[2][6]); acc[2][7] = ffma2(xB.x, w7, acc[2][7]);
        acc[3][0] = ffma2(xB.y, w0, acc[3][0]); acc[3][1] = ffma2(xB.y, w1, acc[3][1]);
        acc[3][2] = ffma2(xB.y, w2, acc[3][2]); acc[3][3] = ffma2(xB.y, w3, acc[3][3]);
        acc[3][4] = ffma2(xB.y, w4, acc[3][4]); acc[3][5] = ffma2(xB.y, w5, acc[3][5]);
        acc[3][6] = ffma2(xB.y, w6, acc[3][6]); acc[3][7] = ffma2(xB.y, w7, acc[3][7]);
    }
    __syncthreads();

    {
        int mj = (tx & 3) << 3;
#pragma unroll
        for (int c = 0; c < 8; c++) {
            int j = j0 + c;
            u64 h[4];
#pragma unroll
            for (int i = 0; i < 4; i++) {
                float2 p = unpack2(acc[i][c]);
                h[i] = pack2(fmaxf(p.x, 0.f), fmaxf(p.y, 0.f));
            }
            ulonglong2 hA; hA.x = h[0]; hA.y = h[1];
            ulonglong2 hB; hB.x = h[2]; hB.y = h[3];
            int base = j * 128 + (r0 ^ mj);
            *(ulonglong2*)&Xs[base] = hA;
            *(ulonglong2*)&Xs[base + 4] = hB;
        }
    }
    for (int i = tid; i < 4096; i += 128) {
        int j = i >> 6, k = i & 63;
        Ws[wpos(k, j)] = W2[i];
    }
    __syncthreads();

    {
        float4 ba = *(const float4*)(b2 + j0);
        float4 bb = *(const float4*)(b2 + j0 + 4);
        u64 d0 = dup2(ba.x), d1 = dup2(ba.y), d2 = dup2(ba.z), d3 = dup2(ba.w);
        u64 d4 = dup2(bb.x), d5 = dup2(bb.y), d6 = dup2(bb.z), d7 = dup2(bb.w);
#pragma unroll
        for (int i = 0; i < 4; i++) {
            acc[i][0] = d0; acc[i][1] = d1; acc[i][2] = d2; acc[i][3] = d3;
            acc[i][4] = d4; acc[i][5] = d5; acc[i][6] = d6; acc[i][7] = d7;
        }
    }

#pragma unroll 8
    for (int k = 0; k < 64; k++) {
        int xb = k * 128 + (r0 ^ ((k >> 3 & 3) << 3));
        ulonglong2 xA = *(const ulonglong2*)&Xs[xb];
        ulonglong2 xB = *(const ulonglong2*)&Xs[xb + 4];
        float4 wa = *(const float4*)&Ws[k * 64 + tx * 4];
        float4 wb = *(const float4*)&Ws[k * 64 + 32 + tx * 4];
        u64 w0 = dup2(wa.x), w1 = dup2(wa.y), w2 = dup2(wa.z), w3 = dup2(wa.w);
        u64 w4 = dup2(wb.x), w5 = dup2(wb.y), w6 = dup2(wb.z), w7 = dup2(wb.w);
        acc[0][0] = ffma2(xA.x, w0, acc[0][0]); acc[0][1] = ffma2(xA.x, w1, acc[0][1]);
        acc[0][2] = ffma2(xA.x, w2, acc[0][2]); acc[0][3] = ffma2(xA.x, w3, acc[0][3]);
        acc[0][4] = ffma2(xA.x, w4, acc[0][4]); acc[0][5] = ffma2(xA.x, w5, acc[0][5]);
        acc[0][6] = ffma2(xA.x, w6, acc[0][6]); acc[0][7] = ffma2(xA.x, w7, acc[0][7]);
        acc[1][0] = ffma2(xA.y, w0, acc[1][0]); acc[1][1] = ffma2(xA.y, w1, acc[1][1]);
        acc[1][2] = ffma2(xA.y, w2, acc[1][2]); acc[1][3] = ffma2(xA.y, w3, acc[1][3]);
        acc[1][4] = ffma2(xA.y, w4, acc[1][4]); acc[1][5] = ffma2(xA.y, w5, acc[1][5]);
        acc[1][6] = ffma2(xA.y, w6, acc[1][6]); acc[1][7] = ffma2(xA.y, w7, acc[1][7]);
        acc[2][0] = ffma2(xB.x, w0, acc[2][0]); acc[2][1] = ffma2(xB.x, w1, acc[2][1]);
        acc[2][2] = ffma2(xB.x, w2, acc[2][2]); acc[2][3] = ffma2(xB.x, w3, acc[2][3]);
        acc[2][4] = ffma2(xB.x, w4, acc[2][4]); acc[2][5] = ffma2(xB.x, w5, acc[2][5]);
        acc[2][6] = ffma2(xB.x, w6, acc[2][6]); acc[2][7] = ffma2(xB.x, w7, acc[2][7]);
        acc[3][0] = ffma2(xB.y, w0, acc[3][0]); acc[3][1] = ffma2(xB.y, w1, acc[3][1]);
        acc[3][2] = ffma2(xB.y, w2, acc[3][2]); acc[3][3] = ffma2(xB.y, w3, acc[3][3]);
        acc[3][4] = ffma2(xB.y, w4, acc[3][4]); acc[3][5] = ffma2(xB.y, w5, acc[3][5]);
        acc[3][6] = ffma2(xB.y, w6, acc[3][6]); acc[3][7] = ffma2(xB.y, w7, acc[3][7]);
    }

    // epilogue: eh=exp(y), px=eh*x, plus off into EP[128:192)
#pragma unroll
    for (int i = 0; i < 4; i++) {
        float2 u[8];
#pragma unroll
        for (int c = 0; c < 8; c++) u[c] = unpack2(acc[i][c]);
#pragma unroll
        for (int half = 0; half < 2; half++) {
            int row = row0 + r0 + 2 * i + half;
            const float* src;
            const float* osrc;
            if (LAYER == 0) {
                if (row < NU) { src = ue + (size_t)row * 64; osrc = uo + (size_t)row * 64; }
                else if (row < NU + NI) { src = ie + (size_t)(row - NU) * 64; osrc = io + (size_t)(row - NU) * 64; }
                else { src = te + (size_t)(row - NU - NI) * 64; osrc = to + (size_t)(row - NU - NI) * 64; }
            } else {
                src = g_embsB + (size_t)row * 64;
                osrc = g_offB + (size_t)row * 64;
            }
            float4 xa = *(const float4*)(src + j0);
            float4 xb = *(const float4*)(src + j0 + 4);
            float4 oa = *(const float4*)(osrc + j0);
            float4 ob = *(const float4*)(osrc + j0 + 4);
            if (LAYER == 0) {  // inputs need relu; g_offB already relu'd
                oa.x = fmaxf(oa.x, 0.f); oa.y = fmaxf(oa.y, 0.f);
                oa.z = fmaxf(oa.z, 0.f); oa.w = fmaxf(oa.w, 0.f);
                ob.x = fmaxf(ob.x, 0.f); ob.y = fmaxf(ob.y, 0.f);
                ob.z = fmaxf(ob.z, 0.f); ob.w = fmaxf(ob.w, 0.f);
            }
            float y0 = half ? u[0].y : u[0].x;
            float y1 = half ? u[1].y : u[1].x;
            float y2 = half ? u[2].y : u[2].x;
            float y3 = half ? u[3].y : u[3].x;
            float y4 = half ? u[4].y : u[4].x;
            float y5 = half ? u[5].y : u[5].x;
            float y6 = half ? u[6].y : u[6].x;
            float y7 = half ? u[7].y : u[7].x;
            float e0 = __expf(y0), e1 = __expf(y1), e2 = __expf(y2), e3 = __expf(y3);
            float e4 = __expf(y4), e5 = __expf(y5), e6 = __expf(y6), e7 = __expf(y7);
            size_t base = (size_t)row * EPS;
            *(float4*)&g_EP[base + j0]           = make_float4(e0, e1, e2, e3);
            *(float4*)&g_EP[base + j0 + 4]       = make_float4(e4, e5, e6, e7);
            *(float4*)&g_EP[base + 64 + j0]      = make_float4(e0 * xa.x, e1 * xa.y, e2 * xa.z, e3 * xa.w);
            *(float4*)&g_EP[base + 64 + j0 + 4]  = make_float4(e4 * xb.x, e5 * xb.y, e6 * xb.z, e7 * xb.w);
            *(float4*)&g_EP[base + 128 + j0]     = oa;
            *(float4*)&g_EP[base + 128 + j0 + 4] = ob;
        }
    }
}

// ---------------- per-node aggregation: single-record gather ----------------
template <int FINAL>
__global__ __launch_bounds__(256) void aggregate_kernel(float* __restrict__ out) {
    int w = (blockIdx.x * blockDim.x + threadIdx.x) >> 5;
    if (w >= NNODES) return;
    int lane = threadIdx.x & 31;
    int half = lane >> 4;
    int fl = (lane & 15) * 4;

    int beg = g_csr_off[w];
    int end = g_csr_off[w + 1];
    const bool is_user = (w < NU);
    const bool is_item = (w >= NU) && (w < NU + NI);

    float4 s = make_float4(0.f, 0.f, 0.f, 0.f);
    float4 n = make_float4(0.f, 0.f, 0.f, 0.f);
    float4 mn = make_float4(INFINITY, INFINITY, INFINITY, INFINITY);
    float4 mx = make_float4(0.f, 0.f, 0.f, 0.f);

    for (int chunk = beg; chunk < end; chunk += 32) {
        int nn = end - chunk; if (nn > 32) nn = 32;
        int tl = 0;
        if (lane < nn) tl = __ldg(&g_csr_tail[chunk + lane]);
#pragma unroll 4
        for (int q = 0; q < nn; q += 2) {
            int idx = q + half;
            int t = __shfl_sync(0xffffffffu, tl, idx & 31);
            if (idx < nn) {
                const float* base = g_EP + (size_t)t * EPS + fl;
                float4 eh = __ldg((const float4*)base);
                float4 px = __ldg((const float4*)(base + 64));

                s.x += eh.x; s.y += eh.y; s.z += eh.z; s.w += eh.w;
                n.x += px.x; n.y += px.y; n.z += px.z; n.w += px.w;

                if (!(is_user && t < NU)) {
                    float4 o = __ldg((const float4*)(base + 128));
                    bool t_item = (t >= NU) && (t < NU + NI);
                    bool t_tag  = (t >= NU + NI);
                    bool do_min = is_user ? t_item : (!is_item);
                    bool do_max = is_user ? t_tag  : is_item;
                    if (do_min) {
                        mn.x = fminf(mn.x, o.x); mn.y = fminf(mn.y, o.y);
                        mn.z = fminf(mn.z, o.z); mn.w = fminf(mn.w, o.w);
                    }
                    if (do_max) {
                        mx.x = fmaxf(mx.x, o.x); mx.y = fmaxf(mx.y, o.y);
                        mx.z = fmaxf(mx.z, o.z); mx.w = fmaxf(mx.w, o.w);
                    }
                }
            }
        }
    }

#define MRG_ADD(v) v += __shfl_xor_sync(0xffffffffu, v, 16)
#define MRG_MIN(v) v = fminf(v, __shfl_xor_sync(0xffffffffu, v, 16))
#define MRG_MAX(v) v = fmaxf(v, __shfl_xor_sync(0xffffffffu, v, 16))
    MRG_ADD(s.x); MRG_ADD(s.y); MRG_ADD(s.z); MRG_ADD(s.w);
    MRG_ADD(n.x); MRG_ADD(n.y); MRG_ADD(n.z); MRG_ADD(n.w);
    MRG_MIN(mn.x); MRG_MIN(mn.y); MRG_MIN(mn.z); MRG_MIN(mn.w);
    MRG_MAX(mx.x); MRG_MAX(mx.y); MRG_MAX(mx.z); MRG_MAX(mx.w);

    float4 a;
    a.x = (s.x > 0.f) ? n.x / s.x : 0.f;
    a.y = (s.y > 0.f) ? n.y / s.y : 0.f;
    a.z = (s.z > 0.f) ? n.z / s.z : 0.f;
    a.w = (s.w > 0.f) ? n.w / s.w : 0.f;

    float ss = a.x * a.x + a.y * a.y + a.z * a.z + a.w * a.w;
#pragma unroll
    for (int of = 8; of; of >>= 1) ss += __shfl_xor_sync(0xffffffffu, ss, of);
    float inv = 1.f / fmaxf(sqrtf(ss), 1e-12f);
    a.x *= inv; a.y *= inv; a.z *= inv; a.w *= inv;

    float4 ov;
    if (is_user) {
        float i0 = isinf(mn.x) ? 0.f : mn.x;
        float i1 = isinf(mn.y) ? 0.f : mn.y;
        float i2 = isinf(mn.z) ? 0.f : mn.z;
        float i3 = isinf(mn.w) ? 0.f : mn.w;
        ov = make_float4(fminf(i0, mx.x), fminf(i1, mx.y), fminf(i2, mx.z), fminf(i3, mx.w));
    } else if (is_item) {
        ov = mx;
    } else {
        ov.x = isinf(mn.x) ? 0.f : mn.x;
        ov.y = isinf(mn.y) ? 0.f : mn.y;
        ov.z = isinf(mn.z) ? 0.f : mn.z;
        ov.w = isinf(mn.w) ? 0.f : mn.w;
    }
    ov.x = fmaxf(ov.x, 0.f); ov.y = fmaxf(ov.y, 0.f);
    ov.z = fmaxf(ov.z, 0.f); ov.w = fmaxf(ov.w, 0.f);

    if (FINAL == 0) {
        size_t base = (size_t)w * 64 + fl;
        if (half == 0) *(float4*)(g_embsB + base) = a;
        else           *(float4*)(g_offB + base)  = ov;
    } else {
        size_t eb, ob;
        if (is_user) {
            eb = (size_t)w * 64;
            ob = (size_t)NU * 64 + (size_t)w * 64;
        } else if (is_item) {
            size_t b2 = (size_t)2 * NU * 64;
            eb = b2 + (size_t)(w - NU) * 64;
            ob = b2 + (size_t)NI * 64 + (size_t)(w - NU) * 64;
        } else {
            size_t b3 = (size_t)2 * (NU + NI) * 64;
            eb = b3 + (size_t)(w - NU - NI) * 64;
            ob = b3 + (size_t)NT * 64 + (size_t)(w - NU - NI) * 64;
        }
        if (half == 0) *(float4*)(out + eb + fl) = a;
        else           *(float4*)(out + ob + fl) = ov;
    }
}

// ---------------- launch ----------------
extern "C" void kernel_launch(void* const* d_in, const int* in_sizes, int n_in,
                              void* d_out, int out_size) {
    const float* user_emb = (const float*)d_in[0];
    const float* user_off = (const float*)d_in[1];
    const float* item_emb = (const float*)d_in[2];
    const float* item_off = (const float*)d_in[3];
    const float* tag_emb  = (const float*)d_in[4];
    const float* tag_off  = (const float*)d_in[5];
    const float* W1 = (const float*)d_in[6];
    const float* b1 = (const float*)d_in[7];
    const float* W2 = (const float*)d_in[8];
    const float* b2 = (const float*)d_in[9];
    const int* head = (const int*)d_in[10];
    const int* tail = (const int*)d_in[11];
    float* out = (float*)d_out;

    const int NB = (NNODES + SCAN_B - 1) / SCAN_B;

    // slot #4 (ncu capture) = mlp<0>; CSR chain completes before aggregate<0>
    zero_deg_kernel<<<(NNODES + 255) / 256, 256>>>(); // 1
    hist_kernel<<<(NE + 255) / 256, 256>>>(head);     // 2
    scan_block_kernel<<<NB, SCAN_B>>>();              // 3
    mlp_kernel<0><<<NNODES / 128, 128>>>(user_emb, item_emb, tag_emb,
                                         user_off, item_off, tag_off,
                                         W1, b1, W2, b2);  // 4 <- profiled
    scan_sums_kernel<<<1, 256>>>(NB);                 // 5
    scan_add_kernel<<<NB, SCAN_B>>>();                // 6
    scatter_kernel<<<(NE + 255) / 256, 256>>>(head, tail);  // 7
    aggregate_kernel<0><<<(NNODES + 7) / 8, 256>>>(out);    // 8
    mlp_kernel<1><<<NNODES / 128, 128>>>(user_emb, item_emb, tag_emb,
                                         user_off, item_off, tag_off,
                                         W1, b1, W2, b2);   // 9
    aggregate_kernel<1><<<(NNODES + 7) / 8, 256>>>(out);    // 10
}

// round 13
// speedup vs baseline: 1.0565x; 1.0565x over previous
#include <cuda_runtime.h>
#include <math.h>

#define NU 100000
#define NI 50000
#define NT 10000
#define NNODES 160000
#define NE 800000
#define DD 64

typedef unsigned long long u64;

// ---------------- device scratch ----------------
__device__ float g_embsB[NNODES * DD];
__device__ float g_offB[NNODES * DD];
__device__ float g_EP[NNODES * 128];     // [0:64) eh=exp(h), [64:128) px=eh*x

__device__ int g_deg[NNODES];
__device__ int g_scan[NNODES];
__device__ int g_csr_off[NNODES + 1];
__device__ int g_pos[NNODES];
__device__ int g_csr_tail[NE];
__device__ int g_bsums[256];

// ---------------- packed f32x2 helpers ----------------
__device__ __forceinline__ u64 pack2(float a, float b) {
    u64 r; asm("mov.b64 %0,{%1,%2};" : "=l"(r) : "f"(a), "f"(b)); return r;
}
__device__ __forceinline__ u64 dup2(float a) {
    u64 r; asm("mov.b64 %0,{%1,%1};" : "=l"(r) : "f"(a)); return r;
}
__device__ __forceinline__ float2 unpack2(u64 v) {
    float2 f; asm("mov.b64 {%0,%1},%2;" : "=f"(f.x), "=f"(f.y) : "l"(v)); return f;
}
__device__ __forceinline__ u64 ffma2(u64 a, u64 b, u64 c) {
    u64 d; asm("fma.rn.f32x2 %0,%1,%2,%3;" : "=l"(d) : "l"(a), "l"(b), "l"(c)); return d;
}
__device__ __forceinline__ u64 addf2(u64 a, u64 b) {
    u64 d; asm("add.rn.f32x2 %0,%1,%2;" : "=l"(d) : "l"(a), "l"(b)); return d;
}

// ---------------- CSR build (multi-kernel, proven fastest) ----------------
__global__ void zero_deg_kernel() {
    int i = blockIdx.x * blockDim.x + threadIdx.x;
    if (i < NNODES) g_deg[i] = 0;
}

__global__ void hist_kernel(const int* __restrict__ head) {
    int e = blockIdx.x * blockDim.x + threadIdx.x;
    if (e < NE) atomicAdd(&g_deg[head[e]], 1);
}

#define SCAN_B 1024
__global__ void scan_block_kernel() {
    __shared__ int sh[SCAN_B];
    int g = blockIdx.x * SCAN_B + threadIdx.x;
    int v = (g < NNODES) ? g_deg[g] : 0;
    sh[threadIdx.x] = v;
    __syncthreads();
    for (int of = 1; of < SCAN_B; of <<= 1) {
        int t = (threadIdx.x >= of) ? sh[threadIdx.x - of] : 0;
        __syncthreads();
        sh[threadIdx.x] += t;
        __syncthreads();
    }
    if (g < NNODES) g_scan[g] = sh[threadIdx.x];
    if (threadIdx.x == SCAN_B - 1) g_bsums[blockIdx.x] = sh[threadIdx.x];
}

__global__ void scan_sums_kernel(int nb) {
    __shared__ int sh[256];
    int v = (threadIdx.x < nb) ? g_bsums[threadIdx.x] : 0;
    sh[threadIdx.x] = v;
    __syncthreads();
    for (int of = 1; of < 256; of <<= 1) {
        int t = (threadIdx.x >= of) ? sh[threadIdx.x - of] : 0;
        __syncthreads();
        sh[threadIdx.x] += t;
        __syncthreads();
    }
    if (threadIdx.x < nb) g_bsums[threadIdx.x] = sh[threadIdx.x] - v;
    if (threadIdx.x == 0) g_csr_off[0] = 0;
}

__global__ void scan_add_kernel() {
    int g = blockIdx.x * SCAN_B + threadIdx.x;
    if (g < NNODES) {
        int inc = g_scan[g] + g_bsums[blockIdx.x];
        g_csr_off[g + 1] = inc;
        g_pos[g] = inc - g_deg[g];
    }
}

__global__ void scatter_kernel(const int* __restrict__ head, const int* __restrict__ tail) {
    int e = blockIdx.x * blockDim.x + threadIdx.x;
    if (e < NE) {
        int h = head[e];
        int p = atomicAdd(&g_pos[h], 1);
        g_csr_tail[p] = tail[e];
    }
}

// ---------------- MLP (R10 shape): 128 thr, tile 128x64, thread 8x8 ----------------
__device__ __forceinline__ int xswz(int k, int r) {
    return k * 128 + (r ^ ((k >> 3 & 3) << 3));
}
__device__ __forceinline__ int wpos(int k, int j) {
    int m = j >> 2;
    return k * 64 + ((m & 1) << 5) + ((m >> 1) << 2) + (j & 3);
}

template <int LAYER>
__global__ __launch_bounds__(128) void mlp_kernel(
    const float* __restrict__ ue, const float* __restrict__ ie, const float* __restrict__ te,
    const float* __restrict__ W1, const float* __restrict__ b1,
    const float* __restrict__ W2, const float* __restrict__ b2) {
    __shared__ __align__(16) float Ws[64 * 64];    // 16 KB
    __shared__ __align__(16) float Xs[64 * 128];   // 32 KB

    const int tid = threadIdx.x;
    const int row0 = blockIdx.x * 128;

    for (int i = tid; i < 4096; i += 128) {
        int j = i >> 6, k = i & 63;
        Ws[wpos(k, j)] = W1[i];
    }
    for (int i = tid; i < 2048; i += 128) {
        int rl = i >> 4, c4 = (i & 15) * 4;
        int row = row0 + rl;
        const float* src;
        if (LAYER == 0) {
            if (row < NU) src = ue + (size_t)row * 64;
            else if (row < NU + NI) src = ie + (size_t)(row - NU) * 64;
            else src = te + (size_t)(row - NU - NI) * 64;
        } else {
            src = g_embsB + (size_t)row * 64;
        }
        float4 v = *(const float4*)(src + c4);
        Xs[xswz(c4 + 0, rl)] = v.x;
        Xs[xswz(c4 + 1, rl)] = v.y;
        Xs[xswz(c4 + 2, rl)] = v.z;
        Xs[xswz(c4 + 3, rl)] = v.w;
    }
    __syncthreads();

    const int tx = tid & 7, ty = tid >> 3;
    const int j0 = tx * 8, r0 = ty * 8;

    u64 acc[4][8];
    {
        float4 ba = *(const float4*)(b1 + j0);
        float4 bb = *(const float4*)(b1 + j0 + 4);
        u64 d0 = dup2(ba.x), d1 = dup2(ba.y), d2 = dup2(ba.z), d3 = dup2(ba.w);
        u64 d4 = dup2(bb.x), d5 = dup2(bb.y), d6 = dup2(bb.z), d7 = dup2(bb.w);
#pragma unroll
        for (int i = 0; i < 4; i++) {
            acc[i][0] = d0; acc[i][1] = d1; acc[i][2] = d2; acc[i][3] = d3;
            acc[i][4] = d4; acc[i][5] = d5; acc[i][6] = d6; acc[i][7] = d7;
        }
    }

#pragma unroll 8
    for (int k = 0; k < 64; k++) {
        int xb = k * 128 + (r0 ^ ((k >> 3 & 3) << 3));
        ulonglong2 xA = *(const ulonglong2*)&Xs[xb];
        ulonglong2 xB = *(const ulonglong2*)&Xs[xb + 4];
        float4 wa = *(const float4*)&Ws[k * 64 + tx * 4];
        float4 wb = *(const float4*)&Ws[k * 64 + 32 + tx * 4];
        u64 w0 = dup2(wa.x), w1 = dup2(wa.y), w2 = dup2(wa.z), w3 = dup2(wa.w);
        u64 w4 = dup2(wb.x), w5 = dup2(wb.y), w6 = dup2(wb.z), w7 = dup2(wb.w);
        acc[0][0] = ffma2(xA.x, w0, acc[0][0]); acc[0][1] = ffma2(xA.x, w1, acc[0][1]);
        acc[0][2] = ffma2(xA.x, w2, acc[0][2]); acc[0][3] = ffma2(xA.x, w3, acc[0][3]);
        acc[0][4] = ffma2(xA.x, w4, acc[0][4]); acc[0][5] = ffma2(xA.x, w5, acc[0][5]);
        acc[0][6] = ffma2(xA.x, w6, acc[0][6]); acc[0][7] = ffma2(xA.x, w7, acc[0][7]);
        acc[1][0] = ffma2(xA.y, w0, acc[1][0]); acc[1][1] = ffma2(xA.y, w1, acc[1][1]);
        acc[1][2] = ffma2(xA.y, w2, acc[1][2]); acc[1][3] = ffma2(xA.y, w3, acc[1][3]);
        acc[1][4] = ffma2(xA.y, w4, acc[1][4]); acc[1][5] = ffma2(xA.y, w5, acc[1][5]);
        acc[1][6] = ffma2(xA.y, w6, acc[1][6]); acc[1][7] = ffma2(xA.y, w7, acc[1][7]);
        acc[2][0] = ffma2(xB.x, w0, acc[2][0]); acc[2][1] = ffma2(xB.x, w1, acc[2][1]);
        acc[2][2] = ffma2(xB.x, w2, acc[2][2]); acc[2][3] = ffma2(xB.x, w3, acc[2][3]);
        acc[2][4] = ffma2(xB.x, w4, acc[2][4]); acc[2][5] = ffma2(xB.x, w5, acc[2][5]);
        acc[2][6] = ffma2(xB.x, w6, acc[2][6]); acc[2][7] = ffma2(xB.x, w7, acc[2][7]);
        acc[3][0] = ffma2(xB.y, w0, acc[3][0]); acc[3][1] = ffma2(xB.y, w1, acc[3][1]);
        acc[3][2] = ffma2(xB.y, w2, acc[3][2]); acc[3][3] = ffma2(xB.y, w3, acc[3][3]);
        acc[3][4] = ffma2(xB.y, w4, acc[3][4]); acc[3][5] = ffma2(xB.y, w5, acc[3][5]);
        acc[3][6] = ffma2(xB.y, w6, acc[3][6]); acc[3][7] = ffma2(xB.y, w7, acc[3][7]);
    }
    __syncthreads();

    {
        int mj = (tx & 3) << 3;
#pragma unroll
        for (int c = 0; c < 8; c++) {
            int j = j0 + c;
            u64 h[4];
#pragma unroll
            for (int i = 0; i < 4; i++) {
                float2 p = unpack2(acc[i][c]);
                h[i] = pack2(fmaxf(p.x, 0.f), fmaxf(p.y, 0.f));
            }
            ulonglong2 hA; hA.x = h[0]; hA.y = h[1];
            ulonglong2 hB; hB.x = h[2]; hB.y = h[3];
            int base = j * 128 + (r0 ^ mj);
            *(ulonglong2*)&Xs[base] = hA;
            *(ulonglong2*)&Xs[base + 4] = hB;
        }
    }
    for (int i = tid; i < 4096; i += 128) {
        int j = i >> 6, k = i & 63;
        Ws[wpos(k, j)] = W2[i];
    }
    __syncthreads();

    {
        float4 ba = *(const float4*)(b2 + j0);
        float4 bb = *(const float4*)(b2 + j0 + 4);
        u64 d0 = dup2(ba.x), d1 = dup2(ba.y), d2 = dup2(ba.z), d3 = dup2(ba.w);
        u64 d4 = dup2(bb.x), d5 = dup2(bb.y), d6 = dup2(bb.z), d7 = dup2(bb.w);
#pragma unroll
        for (int i = 0; i < 4; i++) {
            acc[i][0] = d0; acc[i][1] = d1; acc[i][2] = d2; acc[i][3] = d3;
            acc[i][4] = d4; acc[i][5] = d5; acc[i][6] = d6; acc[i][7] = d7;
        }
    }

#pragma unroll 8
    for (int k = 0; k < 64; k++) {
        int xb = k * 128 + (r0 ^ ((k >> 3 & 3) << 3));
        ulonglong2 xA = *(const ulonglong2*)&Xs[xb];
        ulonglong2 xB = *(const ulonglong2*)&Xs[xb + 4];
        float4 wa = *(const float4*)&Ws[k * 64 + tx * 4];
        float4 wb = *(const float4*)&Ws[k * 64 + 32 + tx * 4];
        u64 w0 = dup2(wa.x), w1 = dup2(wa.y), w2 = dup2(wa.z), w3 = dup2(wa.w);
        u64 w4 = dup2(wb.x), w5 = dup2(wb.y), w6 = dup2(wb.z), w7 = dup2(wb.w);
        acc[0][0] = ffma2(xA.x, w0, acc[0][0]); acc[0][1] = ffma2(xA.x, w1, acc[0][1]);
        acc[0][2] = ffma2(xA.x, w2, acc[0][2]); acc[0][3] = ffma2(xA.x, w3, acc[0][3]);
        acc[0][4] = ffma2(xA.x, w4, acc[0][4]); acc[0][5] = ffma2(xA.x, w5, acc[0][5]);
        acc[0][6] = ffma2(xA.x, w6, acc[0][6]); acc[0][7] = ffma2(xA.x, w7, acc[0][7]);
        acc[1][0] = ffma2(xA.y, w0, acc[1][0]); acc[1][1] = ffma2(xA.y, w1, acc[1][1]);
        acc[1][2] = ffma2(xA.y, w2, acc[1][2]); acc[1][3] = ffma2(xA.y, w3, acc[1][3]);
        acc[1][4] = ffma2(xA.y, w4, acc[1][4]); acc[1][5] = ffma2(xA.y, w5, acc[1][5]);
        acc[1][6] = ffma2(xA.y, w6, acc[1][6]); acc[1][7] = ffma2(xA.y, w7, acc[1][7]);
        acc[2][0] = ffma2(xB.x, w0, acc[2][0]); acc[2][1] = ffma2(xB.x, w1, acc[2][1]);
        acc[2][2] = ffma2(xB.x, w2, acc[2][2]); acc[2][3] = ffma2(xB.x, w3, acc[2][3]);
        acc[2][4] = ffma2(xB.x, w4, acc[2][4]); acc[2][5] = ffma2(xB.x, w5, acc[2][5]);
        acc[2][6] = ffma2(xB.x, w6, acc[2][6]); acc[2][7] = ffma2(xB.x, w7, acc[2][7]);
        acc[3][0] = ffma2(xB.y, w0, acc[3][0]); acc[3][1] = ffma2(xB.y, w1, acc[3][1]);
        acc[3][2] = ffma2(xB.y, w2, acc[3][2]); acc[3][3] = ffma2(xB.y, w3, acc[3][3]);
        acc[3][4] = ffma2(xB.y, w4, acc[3][4]); acc[3][5] = ffma2(xB.y, w5, acc[3][5]);
        acc[3][6] = ffma2(xB.y, w6, acc[3][6]); acc[3][7] = ffma2(xB.y, w7, acc[3][7]);
    }

    // epilogue: eh = exp(y), px = eh * x
#pragma unroll
    for (int i = 0; i < 4; i++) {
        float2 u[8];
#pragma unroll
        for (int c = 0; c < 8; c++) u[c] = unpack2(acc[i][c]);
#pragma unroll
        for (int half = 0; half < 2; half++) {
            int row = row0 + r0 + 2 * i + half;
            const float* src;
            if (LAYER == 0) {
                if (row < NU) src = ue + (size_t)row * 64;
                else if (row < NU + NI) src = ie + (size_t)(row - NU) * 64;
                else src = te + (size_t)(row - NU - NI) * 64;
            } else {
                src = g_embsB + (size_t)row * 64;
            }
            float4 xa = *(const float4*)(src + j0);
            float4 xb = *(const float4*)(src + j0 + 4);
            float y0 = half ? u[0].y : u[0].x;
            float y1 = half ? u[1].y : u[1].x;
            float y2 = half ? u[2].y : u[2].x;
            float y3 = half ? u[3].y : u[3].x;
            float y4 = half ? u[4].y : u[4].x;
            float y5 = half ? u[5].y : u[5].x;
            float y6 = half ? u[6].y : u[6].x;
            float y7 = half ? u[7].y : u[7].x;
            float e0 = __expf(y0), e1 = __expf(y1), e2 = __expf(y2), e3 = __expf(y3);
            float e4 = __expf(y4), e5 = __expf(y5), e6 = __expf(y6), e7 = __expf(y7);
            size_t base = (size_t)row * 128;
            *(float4*)&g_EP[base + j0]          = make_float4(e0, e1, e2, e3);
            *(float4*)&g_EP[base + j0 + 4]      = make_float4(e4, e5, e6, e7);
            *(float4*)&g_EP[base + 64 + j0]     = make_float4(e0 * xa.x, e1 * xa.y, e2 * xa.z, e3 * xa.w);
            *(float4*)&g_EP[base + 64 + j0 + 4] = make_float4(e4 * xb.x, e5 * xb.y, e6 * xb.z, e7 * xb.w);
        }
    }
}

// ---------------- per-node aggregation (R8 shape + packed f32x2 adds) ----------------
template <int FINAL>
__global__ __launch_bounds__(256) void aggregate_kernel(
    const float* __restrict__ uo, const float* __restrict__ io, const float* __restrict__ to,
    float* __restrict__ out) {
    int w = (blockIdx.x * blockDim.x + threadIdx.x) >> 5;
    if (w >= NNODES) return;
    int lane = threadIdx.x & 31;
    int half = lane >> 4;
    int fl = (lane & 15) * 4;

    int beg = g_csr_off[w];
    int end = g_csr_off[w + 1];
    const bool is_user = (w < NU);
    const bool is_item = (w >= NU) && (w < NU + NI);

    u64 s01 = 0, s23 = 0, n01 = 0, n23 = 0;   // packed {f,f} zero == 0ull
    float4 mn = make_float4(INFINITY, INFINITY, INFINITY, INFINITY);
    float4 mx = make_float4(0.f, 0.f, 0.f, 0.f);

    for (int chunk = beg; chunk < end; chunk += 32) {
        int nn = end - chunk; if (nn > 32) nn = 32;
        int tl = 0;
        if (lane < nn) tl = __ldg(&g_csr_tail[chunk + lane]);
#pragma unroll 4
        for (int q = 0; q < nn; q += 2) {
            int idx = q + half;
            int t = __shfl_sync(0xffffffffu, tl, idx & 31);
            if (idx < nn) {
                size_t epb = (size_t)t * 128;
                ulonglong2 eh = __ldg((const ulonglong2*)&g_EP[epb + fl]);
                ulonglong2 px = __ldg((const ulonglong2*)&g_EP[epb + 64 + fl]);

                s01 = addf2(s01, eh.x); s23 = addf2(s23, eh.y);
                n01 = addf2(n01, px.x); n23 = addf2(n23, px.y);

                bool need_off = !(is_user && t < NU);
                if (need_off) {
                    const float* op;
                    if (FINAL == 0) {
                        if (t < NU)           op = uo + (size_t)t * 64;
                        else if (t < NU + NI) op = io + (size_t)(t - NU) * 64;
                        else                  op = to + (size_t)(t - NU - NI) * 64;
                    } else {
                        op = g_offB + (size_t)t * 64;
                    }
                    float4 o = __ldg((const float4*)(op + fl));
                    if (FINAL == 0) {
                        o.x = fmaxf(o.x, 0.f); o.y = fmaxf(o.y, 0.f);
                        o.z = fmaxf(o.z, 0.f); o.w = fmaxf(o.w, 0.f);
                    }
                    bool t_item = (t >= NU) && (t < NU + NI);
                    bool t_tag  = (t >= NU + NI);
                    bool do_min = is_user ? t_item : (!is_item);
                    bool do_max = is_user ? t_tag  : is_item;
                    if (do_min) {
                        mn.x = fminf(mn.x, o.x); mn.y = fminf(mn.y, o.y);
                        mn.z = fminf(mn.z, o.z); mn.w = fminf(mn.w, o.w);
                    }
                    if (do_max) {
                        mx.x = fmaxf(mx.x, o.x); mx.y = fmaxf(mx.y, o.y);
                        mx.z = fmaxf(mx.z, o.z); mx.w = fmaxf(mx.w, o.w);
                    }
                }
            }
        }
    }

    // unpack packed accumulators
    float4 s, n;
    { float2 p = unpack2(s01); s.x = p.x; s.y = p.y; }
    { float2 p = unpack2(s23); s.z = p.x; s.w = p.y; }
    { float2 p = unpack2(n01); n.x = p.x; n.y = p.y; }
    { float2 p = unpack2(n23); n.z = p.x; n.w = p.y; }

#define MRG_ADD(v) v += __shfl_xor_sync(0xffffffffu, v, 16)
#define MRG_MIN(v) v = fminf(v, __shfl_xor_sync(0xffffffffu, v, 16))
#define MRG_MAX(v) v = fmaxf(v, __shfl_xor_sync(0xffffffffu, v, 16))
    MRG_ADD(s.x); MRG_ADD(s.y); MRG_ADD(s.z); MRG_ADD(s.w);
    MRG_ADD(n.x); MRG_ADD(n.y); MRG_ADD(n.z); MRG_ADD(n.w);
    MRG_MIN(mn.x); MRG_MIN(mn.y); MRG_MIN(mn.z); MRG_MIN(mn.w);
    MRG_MAX(mx.x); MRG_MAX(mx.y); MRG_MAX(mx.z); MRG_MAX(mx.w);

    float4 a;
    a.x = (s.x > 0.f) ? n.x / s.x : 0.f;
    a.y = (s.y > 0.f) ? n.y / s.y : 0.f;
    a.z = (s.z > 0.f) ? n.z / s.z : 0.f;
    a.w = (s.w > 0.f) ? n.w / s.w : 0.f;

    float ss = a.x * a.x + a.y * a.y + a.z * a.z + a.w * a.w;
#pragma unroll
    for (int of = 8; of; of >>= 1) ss += __shfl_xor_sync(0xffffffffu, ss, of);
    float inv = 1.f / fmaxf(sqrtf(ss), 1e-12f);
    a.x *= inv; a.y *= inv; a.z *= inv; a.w *= inv;

    float4 ov;
    if (is_user) {
        float i0 = isinf(mn.x) ? 0.f : mn.x;
        float i1 = isinf(mn.y) ? 0.f : mn.y;
        float i2 = isinf(mn.z) ? 0.f : mn.z;
        float i3 = isinf(mn.w) ? 0.f : mn.w;
        ov = make_float4(fminf(i0, mx.x), fminf(i1, mx.y), fminf(i2, mx.z), fminf(i3, mx.w));
    } else if (is_item) {
        ov = mx;
    } else {
        ov.x = isinf(mn.x) ? 0.f : mn.x;
        ov.y = isinf(mn.y) ? 0.f : mn.y;
        ov.z = isinf(mn.z) ? 0.f : mn.z;
        ov.w = isinf(mn.w) ? 0.f : mn.w;
    }
    ov.x = fmaxf(ov.x, 0.f); ov.y = fmaxf(ov.y, 0.f);
    ov.z = fmaxf(ov.z, 0.f); ov.w = fmaxf(ov.w, 0.f);

    if (FINAL == 0) {
        size_t base = (size_t)w * 64 + fl;
        if (half == 0) *(float4*)(g_embsB + base) = a;
        else           *(float4*)(g_offB + base)  = ov;
    } else {
        size_t eb, ob;
        if (is_user) {
            eb = (size_t)w * 64;
            ob = (size_t)NU * 64 + (size_t)w * 64;
        } else if (is_item) {
            size_t b2 = (size_t)2 * NU * 64;
            eb = b2 + (size_t)(w - NU) * 64;
            ob = b2 + (size_t)NI * 64 + (size_t)(w - NU) * 64;
        } else {
            size_t b3 = (size_t)2 * (NU + NI) * 64;
            eb = b3 + (size_t)(w - NU - NI) * 64;
            ob = b3 + (size_t)NT * 64 + (size_t)(w - NU - NI) * 64;
        }
        if (half == 0) *(float4*)(out + eb + fl) = a;
        else           *(float4*)(out + ob + fl) = ov;
    }
}

// ---------------- launch ----------------
extern "C" void kernel_launch(void* const* d_in, const int* in_sizes, int n_in,
                              void* d_out, int out_size) {
    const float* user_emb = (const float*)d_in[0];
    const float* user_off = (const float*)d_in[1];
    const float* item_emb = (const float*)d_in[2];
    const float* item_off = (const float*)d_in[3];
    const float* tag_emb  = (const float*)d_in[4];
    const float* tag_off  = (const float*)d_in[5];
    const float* W1 = (const float*)d_in[6];
    const float* b1 = (const float*)d_in[7];
    const float* W2 = (const float*)d_in[8];
    const float* b2 = (const float*)d_in[9];
    const int* head = (const int*)d_in[10];
    const int* tail = (const int*)d_in[11];
    float* out = (float*)d_out;

    const int NB = (NNODES + SCAN_B - 1) / SCAN_B;

    // slot #4 (ncu capture) = mlp<0>; CSR chain completes before aggregate<0>
    zero_deg_kernel<<<(NNODES + 255) / 256, 256>>>(); // 1
    hist_kernel<<<(NE + 255) / 256, 256>>>(head);     // 2
    scan_block_kernel<<<NB, SCAN_B>>>();              // 3
    mlp_kernel<0><<<NNODES / 128, 128>>>(user_emb, item_emb, tag_emb,
                                         W1, b1, W2, b2);  // 4 <- profiled
    scan_sums_kernel<<<1, 256>>>(NB);                 // 5
    scan_add_kernel<<<NB, SCAN_B>>>();                // 6
    scatter_kernel<<<(NE + 255) / 256, 256>>>(head, tail);  // 7
    aggregate_kernel<0><<<(NNODES + 7) / 8, 256>>>(
        user_off, item_off, tag_off, out);            // 8
    mlp_kernel<1><<<NNODES / 128, 128>>>(user_emb, item_emb, tag_emb,
                                         W1, b1, W2, b2);   // 9
    aggregate_kernel<1><<<(NNODES + 7) / 8, 256>>>(
        user_off, item_off, tag_off, out);            // 10
}

// round 15
// speedup vs baseline: 1.0694x; 1.0122x over previous
#include <cuda_runtime.h>
#include <math.h>

#define NU 100000
#define NI 50000
#define NT 10000
#define NNODES 160000
#define NE 800000
#define DD 64

typedef unsigned long long u64;

// ---------------- device scratch ----------------
__device__ float g_embsB[NNODES * DD];
__device__ float g_offB[NNODES * DD];
__device__ float g_EP[NNODES * 128];     // [0:64) eh=exp(h), [64:128) px=eh*x

__device__ int g_deg[NNODES];
__device__ int g_scan[NNODES];
__device__ int g_csr_off[NNODES + 1];
__device__ int g_pos[NNODES];
__device__ int g_csr_tail[NE];
__device__ int g_bsums[256];

// ---------------- packed f32x2 helpers ----------------
__device__ __forceinline__ u64 pack2(float a, float b) {
    u64 r; asm("mov.b64 %0,{%1,%2};" : "=l"(r) : "f"(a), "f"(b)); return r;
}
__device__ __forceinline__ u64 dup2(float a) {
    u64 r; asm("mov.b64 %0,{%1,%1};" : "=l"(r) : "f"(a)); return r;
}
__device__ __forceinline__ float2 unpack2(u64 v) {
    float2 f; asm("mov.b64 {%0,%1},%2;" : "=f"(f.x), "=f"(f.y) : "l"(v)); return f;
}
__device__ __forceinline__ u64 ffma2(u64 a, u64 b, u64 c) {
    u64 d; asm("fma.rn.f32x2 %0,%1,%2,%3;" : "=l"(d) : "l"(a), "l"(b), "l"(c)); return d;
}
__device__ __forceinline__ u64 addf2(u64 a, u64 b) {
    u64 d; asm("add.rn.f32x2 %0,%1,%2;" : "=l"(d) : "l"(a), "l"(b)); return d;
}
__device__ __forceinline__ float sqrt_approx(float x) {
    float r; asm("sqrt.approx.f32 %0,%1;" : "=f"(r) : "f"(x)); return r;
}
__device__ __forceinline__ float rcp_approx(float x) {
    float r; asm("rcp.approx.f32 %0,%1;" : "=f"(r) : "f"(x)); return r;
}

// ---------------- CSR build (multi-kernel, proven fastest) ----------------
__global__ void zero_deg_kernel() {
    int i = blockIdx.x * blockDim.x + threadIdx.x;
    if (i < NNODES) g_deg[i] = 0;
}

__global__ void hist_kernel(const int* __restrict__ head) {
    int e = blockIdx.x * blockDim.x + threadIdx.x;
    if (e < NE) atomicAdd(&g_deg[head[e]], 1);
}

#define SCAN_B 1024
__global__ void scan_block_kernel() {
    __shared__ int sh[SCAN_B];
    int g = blockIdx.x * SCAN_B + threadIdx.x;
    int v = (g < NNODES) ? g_deg[g] : 0;
    sh[threadIdx.x] = v;
    __syncthreads();
    for (int of = 1; of < SCAN_B; of <<= 1) {
        int t = (threadIdx.x >= of) ? sh[threadIdx.x - of] : 0;
        __syncthreads();
        sh[threadIdx.x] += t;
        __syncthreads();
    }
    if (g < NNODES) g_scan[g] = sh[threadIdx.x];
    if (threadIdx.x == SCAN_B - 1) g_bsums[blockIdx.x] = sh[threadIdx.x];
}

__global__ void scan_sums_kernel(int nb) {
    __shared__ int sh[256];
    int v = (threadIdx.x < nb) ? g_bsums[threadIdx.x] : 0;
    sh[threadIdx.x] = v;
    __syncthreads();
    for (int of = 1; of < 256; of <<= 1) {
        int t = (threadIdx.x >= of) ? sh[threadIdx.x - of] : 0;
        __syncthreads();
        sh[threadIdx.x] += t;
        __syncthreads();
    }
    if (threadIdx.x < nb) g_bsums[threadIdx.x] = sh[threadIdx.x] - v;
    if (threadIdx.x == 0) g_csr_off[0] = 0;
}

__global__ void scan_add_kernel() {
    int g = blockIdx.x * SCAN_B + threadIdx.x;
    if (g < NNODES) {
        int inc = g_scan[g] + g_bsums[blockIdx.x];
        g_csr_off[g + 1] = inc;
        g_pos[g] = inc - g_deg[g];
    }
}

__global__ void scatter_kernel(const int* __restrict__ head, const int* __restrict__ tail) {
    int e = blockIdx.x * blockDim.x + threadIdx.x;
    if (e < NE) {
        int h = head[e];
        int p = atomicAdd(&g_pos[h], 1);
        g_csr_tail[p] = tail[e];
    }
}

// ---------------- MLP (R10 shape): 128 thr, tile 128x64, thread 8x8 ----------------
__device__ __forceinline__ int xswz(int k, int r) {
    return k * 128 + (r ^ ((k >> 3 & 3) << 3));
}
__device__ __forceinline__ int wpos(int k, int j) {
    int m = j >> 2;
    return k * 64 + ((m & 1) << 5) + ((m >> 1) << 2) + (j & 3);
}

template <int LAYER>
__global__ __launch_bounds__(128) void mlp_kernel(
    const float* __restrict__ ue, const float* __restrict__ ie, const float* __restrict__ te,
    const float* __restrict__ W1, const float* __restrict__ b1,
    const float* __restrict__ W2, const float* __restrict__ b2) {
    __shared__ __align__(16) float Ws[64 * 64];    // 16 KB
    __shared__ __align__(16) float Xs[64 * 128];   // 32 KB

    const int tid = threadIdx.x;
    const int row0 = blockIdx.x * 128;

    for (int i = tid; i < 4096; i += 128) {
        int j = i >> 6, k = i & 63;
        Ws[wpos(k, j)] = W1[i];
    }
    for (int i = tid; i < 2048; i += 128) {
        int rl = i >> 4, c4 = (i & 15) * 4;
        int row = row0 + rl;
        const float* src;
        if (LAYER == 0) {
            if (row < NU) src = ue + (size_t)row * 64;
            else if (row < NU + NI) src = ie + (size_t)(row - NU) * 64;
            else src = te + (size_t)(row - NU - NI) * 64;
        } else {
            src = g_embsB + (size_t)row * 64;
        }
        float4 v = *(const float4*)(src + c4);
        Xs[xswz(c4 + 0, rl)] = v.x;
        Xs[xswz(c4 + 1, rl)] = v.y;
        Xs[xswz(c4 + 2, rl)] = v.z;
        Xs[xswz(c4 + 3, rl)] = v.w;
    }
    __syncthreads();

    const int tx = tid & 7, ty = tid >> 3;
    const int j0 = tx * 8, r0 = ty * 8;

    u64 acc[4][8];
    {
        float4 ba = *(const float4*)(b1 + j0);
        float4 bb = *(const float4*)(b1 + j0 + 4);
        u64 d0 = dup2(ba.x), d1 = dup2(ba.y), d2 = dup2(ba.z), d3 = dup2(ba.w);
        u64 d4 = dup2(bb.x), d5 = dup2(bb.y), d6 = dup2(bb.z), d7 = dup2(bb.w);
#pragma unroll
        for (int i = 0; i < 4; i++) {
            acc[i][0] = d0; acc[i][1] = d1; acc[i][2] = d2; acc[i][3] = d3;
            acc[i][4] = d4; acc[i][5] = d5; acc[i][6] = d6; acc[i][7] = d7;
        }
    }

#pragma unroll 8
    for (int k = 0; k < 64; k++) {
        int xb = k * 128 + (r0 ^ ((k >> 3 & 3) << 3));
        ulonglong2 xA = *(const ulonglong2*)&Xs[xb];
        ulonglong2 xB = *(const ulonglong2*)&Xs[xb + 4];
        float4 wa = *(const float4*)&Ws[k * 64 + tx * 4];
        float4 wb = *(const float4*)&Ws[k * 64 + 32 + tx * 4];
        u64 w0 = dup2(wa.x), w1 = dup2(wa.y), w2 = dup2(wa.z), w3 = dup2(wa.w);
        u64 w4 = dup2(wb.x), w5 = dup2(wb.y), w6 = dup2(wb.z), w7 = dup2(wb.w);
        acc[0][0] = ffma2(xA.x, w0, acc[0][0]); acc[0][1] = ffma2(xA.x, w1, acc[0][1]);
        acc[0][2] = ffma2(xA.x, w2, acc[0][2]); acc[0][3] = ffma2(xA.x, w3, acc[0][3]);
        acc[0][4] = ffma2(xA.x, w4, acc[0][4]); acc[0][5] = ffma2(xA.x, w5, acc[0][5]);
        acc[0][6] = ffma2(xA.x, w6, acc[0][6]); acc[0][7] = ffma2(xA.x, w7, acc[0][7]);
        acc[1][0] = ffma2(xA.y, w0, acc[1][0]); acc[1][1] = ffma2(xA.y, w1, acc[1][1]);
        acc[1][2] = ffma2(xA.y, w2, acc[1][2]); acc[1][3] = ffma2(xA.y, w3, acc[1][3]);
        acc[1][4] = ffma2(xA.y, w4, acc[1][4]); acc[1][5] = ffma2(xA.y, w5, acc[1][5]);
        acc[1][6] = ffma2(xA.y, w6, acc[1][6]); acc[1][7] = ffma2(xA.y, w7, acc[1][7]);
        acc[2][0] = ffma2(xB.x, w0, acc[2][0]); acc[2][1] = ffma2(xB.x, w1, acc[2][1]);
        acc[2][2] = ffma2(xB.x, w2, acc[2][2]); acc[2][3] = ffma2(xB.x, w3, acc[2][3]);
        acc[2][4] = ffma2(xB.x, w4, acc[2][4]); acc[2][5] = ffma2(xB.x, w5, acc[2][5]);
        acc[2][6] = ffma2(xB.x, w6, acc[2][6]); acc[2][7] = ffma2(xB.x, w7, acc[2][7]);
        acc[3][0] = ffma2(xB.y, w0, acc[3][0]); acc[3][1] = ffma2(xB.y, w1, acc[3][1]);
        acc[3][2] = ffma2(xB.y, w2, acc[3][2]); acc[3][3] = ffma2(xB.y, w3, acc[3][3]);
        acc[3][4] = ffma2(xB.y, w4, acc[3][4]); acc[3][5] = ffma2(xB.y, w5, acc[3][5]);
        acc[3][6] = ffma2(xB.y, w6, acc[3][6]); acc[3][7] = ffma2(xB.y, w7, acc[3][7]);
    }
    __syncthreads();

    {
        int mj = (tx & 3) << 3;
#pragma unroll
        for (int c = 0; c < 8; c++) {
            int j = j0 + c;
            u64 h[4];
#pragma unroll
            for (int i = 0; i < 4; i++) {
                float2 p = unpack2(acc[i][c]);
                h[i] = pack2(fmaxf(p.x, 0.f), fmaxf(p.y, 0.f));
            }
            ulonglong2 hA; hA.x = h[0]; hA.y = h[1];
            ulonglong2 hB; hB.x = h[2]; hB.y = h[3];
            int base = j * 128 + (r0 ^ mj);
            *(ulonglong2*)&Xs[base] = hA;
            *(ulonglong2*)&Xs[base + 4] = hB;
        }
    }
    for (int i = tid; i < 4096; i += 128) {
        int j = i >> 6, k = i & 63;
        Ws[wpos(k, j)] = W2[i];
    }
    __syncthreads();

    {
        float4 ba = *(const float4*)(b2 + j0);
        float4 bb = *(const float4*)(b2 + j0 + 4);
        u64 d0 = dup2(ba.x), d1 = dup2(ba.y), d2 = dup2(ba.z), d3 = dup2(ba.w);
        u64 d4 = dup2(bb.x), d5 = dup2(bb.y), d6 = dup2(bb.z), d7 = dup2(bb.w);
#pragma unroll
        for (int i = 0; i < 4; i++) {
            acc[i][0] = d0; acc[i][1] = d1; acc[i][2] = d2; acc[i][3] = d3;
            acc[i][4] = d4; acc[i][5] = d5; acc[i][6] = d6; acc[i][7] = d7;
        }
    }

#pragma unroll 8
    for (int k = 0; k < 64; k++) {
        int xb = k * 128 + (r0 ^ ((k >> 3 & 3) << 3));
        ulonglong2 xA = *(const ulonglong2*)&Xs[xb];
        ulonglong2 xB = *(const ulonglong2*)&Xs[xb + 4];
        float4 wa = *(const float4*)&Ws[k * 64 + tx * 4];
        float4 wb = *(const float4*)&Ws[k * 64 + 32 + tx * 4];
        u64 w0 = dup2(wa.x), w1 = dup2(wa.y), w2 = dup2(wa.z), w3 = dup2(wa.w);
        u64 w4 = dup2(wb.x), w5 = dup2(wb.y), w6 = dup2(wb.z), w7 = dup2(wb.w);
        acc[0][0] = ffma2(xA.x, w0, acc[0][0]); acc[0][1] = ffma2(xA.x, w1, acc[0][1]);
        acc[0][2] = ffma2(xA.x, w2, acc[0][2]); acc[0][3] = ffma2(xA.x, w3, acc[0][3]);
        acc[0][4] = ffma2(xA.x, w4, acc[0][4]); acc[0][5] = ffma2(xA.x, w5, acc[0][5]);
        acc[0][6] = ffma2(xA.x, w6, acc[0][6]); acc[0][7] = ffma2(xA.x, w7, acc[0][7]);
        acc[1][0] = ffma2(xA.y, w0, acc[1][0]); acc[1][1] = ffma2(xA.y, w1, acc[1][1]);
        acc[1][2] = ffma2(xA.y, w2, acc[1][2]); acc[1][3] = ffma2(xA.y, w3, acc[1][3]);
        acc[1][4] = ffma2(xA.y, w4, acc[1][4]); acc[1][5] = ffma2(xA.y, w5, acc[1][5]);
        acc[1][6] = ffma2(xA.y, w6, acc[1][6]); acc[1][7] = ffma2(xA.y, w7, acc[1][7]);
        acc[2][0] = ffma2(xB.x, w0, acc[2][0]); acc[2][1] = ffma2(xB.x, w1, acc[2][1]);
        acc[2][2] = ffma2(xB.x, w2, acc[2][2]); acc[2][3] = ffma2(xB.x, w3, acc[2][3]);
        acc[2][4] = ffma2(xB.x, w4, acc[2][4]); acc[2][5] = ffma2(xB.x, w5, acc[2][5]);
        acc[2][6] = ffma2(xB.x, w6, acc[2][6]); acc[2][7] = ffma2(xB.x, w7, acc[2][7]);
        acc[3][0] = ffma2(xB.y, w0, acc[3][0]); acc[3][1] = ffma2(xB.y, w1, acc[3][1]);
        acc[3][2] = ffma2(xB.y, w2, acc[3][2]); acc[3][3] = ffma2(xB.y, w3, acc[3][3]);
        acc[3][4] = ffma2(xB.y, w4, acc[3][4]); acc[3][5] = ffma2(xB.y, w5, acc[3][5]);
        acc[3][6] = ffma2(xB.y, w6, acc[3][6]); acc[3][7] = ffma2(xB.y, w7, acc[3][7]);
    }

    // epilogue: eh = exp(y), px = eh * x
#pragma unroll
    for (int i = 0; i < 4; i++) {
        float2 u[8];
#pragma unroll
        for (int c = 0; c < 8; c++) u[c] = unpack2(acc[i][c]);
#pragma unroll
        for (int half = 0; half < 2; half++) {
            int row = row0 + r0 + 2 * i + half;
            const float* src;
            if (LAYER == 0) {
                if (row < NU) src = ue + (size_t)row * 64;
                else if (row < NU + NI) src = ie + (size_t)(row - NU) * 64;
                else src = te + (size_t)(row - NU - NI) * 64;
            } else {
                src = g_embsB + (size_t)row * 64;
            }
            float4 xa = *(const float4*)(src + j0);
            float4 xb = *(const float4*)(src + j0 + 4);
            float y0 = half ? u[0].y : u[0].x;
            float y1 = half ? u[1].y : u[1].x;
            float y2 = half ? u[2].y : u[2].x;
            float y3 = half ? u[3].y : u[3].x;
            float y4 = half ? u[4].y : u[4].x;
            float y5 = half ? u[5].y : u[5].x;
            float y6 = half ? u[6].y : u[6].x;
            float y7 = half ? u[7].y : u[7].x;
            float e0 = __expf(y0), e1 = __expf(y1), e2 = __expf(y2), e3 = __expf(y3);
            float e4 = __expf(y4), e5 = __expf(y5), e6 = __expf(y6), e7 = __expf(y7);
            size_t base = (size_t)row * 128;
            *(float4*)&g_EP[base + j0]          = make_float4(e0, e1, e2, e3);
            *(float4*)&g_EP[base + j0 + 4]      = make_float4(e4, e5, e6, e7);
            *(float4*)&g_EP[base + 64 + j0]     = make_float4(e0 * xa.x, e1 * xa.y, e2 * xa.z, e3 * xa.w);
            *(float4*)&g_EP[base + 64 + j0 + 4] = make_float4(e4 * xb.x, e5 * xb.y, e6 * xb.z, e7 * xb.w);
        }
    }
}

// ---------------- per-node aggregation (R8 shape + packed adds + fast-math epilogue) ----------------
template <int FINAL>
__global__ __launch_bounds__(256) void aggregate_kernel(
    const float* __restrict__ uo, const float* __restrict__ io, const float* __restrict__ to,
    float* __restrict__ out) {
    int w = (blockIdx.x * blockDim.x + threadIdx.x) >> 5;
    if (w >= NNODES) return;
    int lane = threadIdx.x & 31;
    int half = lane >> 4;
    int fl = (lane & 15) * 4;

    int beg = g_csr_off[w];
    int end = g_csr_off[w + 1];
    const bool is_user = (w < NU);
    const bool is_item = (w >= NU) && (w < NU + NI);

    u64 s01 = 0, s23 = 0, n01 = 0, n23 = 0;
    float4 mn = make_float4(INFINITY, INFINITY, INFINITY, INFINITY);
    float4 mx = make_float4(0.f, 0.f, 0.f, 0.f);

    for (int chunk = beg; chunk < end; chunk += 32) {
        int nn = end - chunk; if (nn > 32) nn = 32;
        int tl = 0;
        if (lane < nn) tl = __ldg(&g_csr_tail[chunk + lane]);
#pragma unroll 4
        for (int q = 0; q < nn; q += 2) {
            int idx = q + half;
            int t = __shfl_sync(0xffffffffu, tl, idx & 31);
            if (idx < nn) {
                size_t epb = (size_t)t * 128;
                ulonglong2 eh = __ldg((const ulonglong2*)&g_EP[epb + fl]);
                ulonglong2 px = __ldg((const ulonglong2*)&g_EP[epb + 64 + fl]);

                s01 = addf2(s01, eh.x); s23 = addf2(s23, eh.y);
                n01 = addf2(n01, px.x); n23 = addf2(n23, px.y);

                bool need_off = !(is_user && t < NU);
                if (need_off) {
                    const float* op;
                    if (FINAL == 0) {
                        if (t < NU)           op = uo + (size_t)t * 64;
                        else if (t < NU + NI) op = io + (size_t)(t - NU) * 64;
                        else                  op = to + (size_t)(t - NU - NI) * 64;
                    } else {
                        op = g_offB + (size_t)t * 64;
                    }
                    float4 o = __ldg((const float4*)(op + fl));
                    if (FINAL == 0) {
                        o.x = fmaxf(o.x, 0.f); o.y = fmaxf(o.y, 0.f);
                        o.z = fmaxf(o.z, 0.f); o.w = fmaxf(o.w, 0.f);
                    }
                    bool t_item = (t >= NU) && (t < NU + NI);
                    bool t_tag  = (t >= NU + NI);
                    bool do_min = is_user ? t_item : (!is_item);
                    bool do_max = is_user ? t_tag  : is_item;
                    if (do_min) {
                        mn.x = fminf(mn.x, o.x); mn.y = fminf(mn.y, o.y);
                        mn.z = fminf(mn.z, o.z); mn.w = fminf(mn.w, o.w);
                    }
                    if (do_max) {
                        mx.x = fmaxf(mx.x, o.x); mx.y = fmaxf(mx.y, o.y);
                        mx.z = fmaxf(mx.z, o.z); mx.w = fmaxf(mx.w, o.w);
                    }
                }
            }
        }
    }

    float4 s, n;
    { float2 p = unpack2(s01); s.x = p.x; s.y = p.y; }
    { float2 p = unpack2(s23); s.z = p.x; s.w = p.y; }
    { float2 p = unpack2(n01); n.x = p.x; n.y = p.y; }
    { float2 p = unpack2(n23); n.z = p.x; n.w = p.y; }

#define MRG_ADD(v) v += __shfl_xor_sync(0xffffffffu, v, 16)
#define MRG_MIN(v) v = fminf(v, __shfl_xor_sync(0xffffffffu, v, 16))
#define MRG_MAX(v) v = fmaxf(v, __shfl_xor_sync(0xffffffffu, v, 16))
    MRG_ADD(s.x); MRG_ADD(s.y); MRG_ADD(s.z); MRG_ADD(s.w);
    MRG_ADD(n.x); MRG_ADD(n.y); MRG_ADD(n.z); MRG_ADD(n.w);
    MRG_MIN(mn.x); MRG_MIN(mn.y); MRG_MIN(mn.z); MRG_MIN(mn.w);
    MRG_MAX(mx.x); MRG_MAX(mx.y); MRG_MAX(mx.z); MRG_MAX(mx.w);

    // fast divides: s > 0 guaranteed when any edge present; guard preserves empty-seg = 0
    float4 a;
    a.x = (s.x > 0.f) ? __fdividef(n.x, s.x) : 0.f;
    a.y = (s.y > 0.f) ? __fdividef(n.y, s.y) : 0.f;
    a.z = (s.z > 0.f) ? __fdividef(n.z, s.z) : 0.f;
    a.w = (s.w > 0.f) ? __fdividef(n.w, s.w) : 0.f;

    float ss = a.x * a.x + a.y * a.y + a.z * a.z + a.w * a.w;
#pragma unroll
    for (int of = 8; of; of >>= 1) ss += __shfl_xor_sync(0xffffffffu, ss, of);
    float inv = rcp_approx(fmaxf(sqrt_approx(ss), 1e-12f));
    a.x *= inv; a.y *= inv; a.z *= inv; a.w *= inv;

    float4 ov;
    if (is_user) {
        float i0 = isinf(mn.x) ? 0.f : mn.x;
        float i1 = isinf(mn.y) ? 0.f : mn.y;
        float i2 = isinf(mn.z) ? 0.f : mn.z;
        float i3 = isinf(mn.w) ? 0.f : mn.w;
        ov = make_float4(fminf(i0, mx.x), fminf(i1, mx.y), fminf(i2, mx.z), fminf(i3, mx.w));
    } else if (is_item) {
        ov = mx;
    } else {
        ov.x = isinf(mn.x) ? 0.f : mn.x;
        ov.y = isinf(mn.y) ? 0.f : mn.y;
        ov.z = isinf(mn.z) ? 0.f : mn.z;
        ov.w = isinf(mn.w) ? 0.f : mn.w;
    }
    ov.x = fmaxf(ov.x, 0.f); ov.y = fmaxf(ov.y, 0.f);
    ov.z = fmaxf(ov.z, 0.f); ov.w = fmaxf(ov.w, 0.f);

    if (FINAL == 0) {
        size_t base = (size_t)w * 64 + fl;
        if (half == 0) *(float4*)(g_embsB + base) = a;
        else           *(float4*)(g_offB + base)  = ov;
    } else {
        size_t eb, ob;
        if (is_user) {
            eb = (size_t)w * 64;
            ob = (size_t)NU * 64 + (size_t)w * 64;
        } else if (is_item) {
            size_t b2 = (size_t)2 * NU * 64;
            eb = b2 + (size_t)(w - NU) * 64;
            ob = b2 + (size_t)NI * 64 + (size_t)(w - NU) * 64;
        } else {
            size_t b3 = (size_t)2 * (NU + NI) * 64;
            eb = b3 + (size_t)(w - NU - NI) * 64;
            ob = b3 + (size_t)NT * 64 + (size_t)(w - NU - NI) * 64;
        }
        if (half == 0) *(float4*)(out + eb + fl) = a;
        else           *(float4*)(out + ob + fl) = ov;
    }
}

// ---------------- launch ----------------
extern "C" void kernel_launch(void* const* d_in, const int* in_sizes, int n_in,
                              void* d_out, int out_size) {
    const float* user_emb = (const float*)d_in[0];
    const float* user_off = (const float*)d_in[1];
    const float* item_emb = (const float*)d_in[2];
    const float* item_off = (const float*)d_in[3];
    const float* tag_emb  = (const float*)d_in[4];
    const float* tag_off  = (const float*)d_in[5];
    const float* W1 = (const float*)d_in[6];
    const float* b1 = (const float*)d_in[7];
    const float* W2 = (const float*)d_in[8];
    const float* b2 = (const float*)d_in[9];
    const int* head = (const int*)d_in[10];
    const int* tail = (const int*)d_in[11];
    float* out = (float*)d_out;

    const int NB = (NNODES + SCAN_B - 1) / SCAN_B;

    // slot #4 (ncu capture) = mlp<0>; CSR chain completes before aggregate<0>
    zero_deg_kernel<<<(NNODES + 255) / 256, 256>>>(); // 1
    hist_kernel<<<(NE + 255) / 256, 256>>>(head);     // 2
    scan_block_kernel<<<NB, SCAN_B>>>();              // 3
    mlp_kernel<0><<<NNODES / 128, 128>>>(user_emb, item_emb, tag_emb,
                                         W1, b1, W2, b2);  // 4 <- profiled
    scan_sums_kernel<<<1, 256>>>(NB);                 // 5
    scan_add_kernel<<<NB, SCAN_B>>>();                // 6
    scatter_kernel<<<(NE + 255) / 256, 256>>>(head, tail);  // 7
    aggregate_kernel<0><<<(NNODES + 7) / 8, 256>>>(
        user_off, item_off, tag_off, out);            // 8
    mlp_kernel<1><<<NNODES / 128, 128>>>(user_emb, item_emb, tag_emb,
                                         W1, b1, W2, b2);   // 9
    aggregate_kernel<1><<<(NNODES + 7) / 8, 256>>>(
        user_off, item_off, tag_off, out);            // 10
}

// round 16
// speedup vs baseline: 1.2066x; 1.1284x over previous
#include <cuda_runtime.h>
#include <cuda_fp16.h>
#include <math.h>

#define NU 100000
#define NI 50000
#define NT 10000
#define NNODES 160000
#define NE 800000
#define DD 64

typedef unsigned long long u64;

// ---------------- device scratch ----------------
__device__ float g_embsB[NNODES * DD];
__device__ float g_offB[NNODES * DD];
// fp16 EP: per node 128 halfs; group g (features 4g..4g+3) at halfs [8g..8g+8):
// {eh[4g..4g+3], px[4g..4g+3]}
__device__ __half g_EPh[NNODES * 128];

__device__ int g_deg[NNODES];
__device__ int g_scan[NNODES];
__device__ int g_csr_off[NNODES + 1];
__device__ int g_pos[NNODES];
__device__ int g_csr_tail[NE];
__device__ int g_bsums[256];

// ---------------- packed helpers ----------------
__device__ __forceinline__ u64 pack2(float a, float b) {
    u64 r; asm("mov.b64 %0,{%1,%2};" : "=l"(r) : "f"(a), "f"(b)); return r;
}
__device__ __forceinline__ u64 dup2(float a) {
    u64 r; asm("mov.b64 %0,{%1,%1};" : "=l"(r) : "f"(a)); return r;
}
__device__ __forceinline__ float2 unpack2(u64 v) {
    float2 f; asm("mov.b64 {%0,%1},%2;" : "=f"(f.x), "=f"(f.y) : "l"(v)); return f;
}
__device__ __forceinline__ u64 ffma2(u64 a, u64 b, u64 c) {
    u64 d; asm("fma.rn.f32x2 %0,%1,%2,%3;" : "=l"(d) : "l"(a), "l"(b), "l"(c)); return d;
}
__device__ __forceinline__ float sqrt_approx(float x) {
    float r; asm("sqrt.approx.f32 %0,%1;" : "=f"(r) : "f"(x)); return r;
}
__device__ __forceinline__ float rcp_approx(float x) {
    float r; asm("rcp.approx.f32 %0,%1;" : "=f"(r) : "f"(x)); return r;
}
__device__ __forceinline__ unsigned h2bits(float lo, float hi) {
    __half2 h = __floats2half2_rn(lo, hi);
    return *(unsigned*)&h;
}
__device__ __forceinline__ float2 h2f2(unsigned bits) {
    __half2 h = *(__half2*)&bits;
    return __half22float2(h);
}

// ---------------- CSR build (multi-kernel, proven fastest) ----------------
__global__ void zero_deg_kernel() {
    int i = blockIdx.x * blockDim.x + threadIdx.x;
    if (i < NNODES) g_deg[i] = 0;
}

__global__ void hist_kernel(const int* __restrict__ head) {
    int e = blockIdx.x * blockDim.x + threadIdx.x;
    if (e < NE) atomicAdd(&g_deg[head[e]], 1);
}

#define SCAN_B 1024
__global__ void scan_block_kernel() {
    __shared__ int sh[SCAN_B];
    int g = blockIdx.x * SCAN_B + threadIdx.x;
    int v = (g < NNODES) ? g_deg[g] : 0;
    sh[threadIdx.x] = v;
    __syncthreads();
    for (int of = 1; of < SCAN_B; of <<= 1) {
        int t = (threadIdx.x >= of) ? sh[threadIdx.x - of] : 0;
        __syncthreads();
        sh[threadIdx.x] += t;
        __syncthreads();
    }
    if (g < NNODES) g_scan[g] = sh[threadIdx.x];
    if (threadIdx.x == SCAN_B - 1) g_bsums[blockIdx.x] = sh[threadIdx.x];
}

__global__ void scan_sums_kernel(int nb) {
    __shared__ int sh[256];
    int v = (threadIdx.x < nb) ? g_bsums[threadIdx.x] : 0;
    sh[threadIdx.x] = v;
    __syncthreads();
    for (int of = 1; of < 256; of <<= 1) {
        int t = (threadIdx.x >= of) ? sh[threadIdx.x - of] : 0;
        __syncthreads();
        sh[threadIdx.x] += t;
        __syncthreads();
    }
    if (threadIdx.x < nb) g_bsums[threadIdx.x] = sh[threadIdx.x] - v;
    if (threadIdx.x == 0) g_csr_off[0] = 0;
}

__global__ void scan_add_kernel() {
    int g = blockIdx.x * SCAN_B + threadIdx.x;
    if (g < NNODES) {
        int inc = g_scan[g] + g_bsums[blockIdx.x];
        g_csr_off[g + 1] = inc;
        g_pos[g] = inc - g_deg[g];
    }
}

__global__ void scatter_kernel(const int* __restrict__ head, const int* __restrict__ tail) {
    int e = blockIdx.x * blockDim.x + threadIdx.x;
    if (e < NE) {
        int h = head[e];
        int p = atomicAdd(&g_pos[h], 1);
        g_csr_tail[p] = tail[e];
    }
}

// ---------------- MLP (R10 shape): 128 thr, tile 128x64, thread 8x8 ----------------
__device__ __forceinline__ int xswz(int k, int r) {
    return k * 128 + (r ^ ((k >> 3 & 3) << 3));
}
__device__ __forceinline__ int wpos(int k, int j) {
    int m = j >> 2;
    return k * 64 + ((m & 1) << 5) + ((m >> 1) << 2) + (j & 3);
}

template <int LAYER>
__global__ __launch_bounds__(128) void mlp_kernel(
    const float* __restrict__ ue, const float* __restrict__ ie, const float* __restrict__ te,
    const float* __restrict__ W1, const float* __restrict__ b1,
    const float* __restrict__ W2, const float* __restrict__ b2) {
    __shared__ __align__(16) float Ws[64 * 64];    // 16 KB
    __shared__ __align__(16) float Xs[64 * 128];   // 32 KB

    const int tid = threadIdx.x;
    const int row0 = blockIdx.x * 128;

    for (int i = tid; i < 4096; i += 128) {
        int j = i >> 6, k = i & 63;
        Ws[wpos(k, j)] = W1[i];
    }
    for (int i = tid; i < 2048; i += 128) {
        int rl = i >> 4, c4 = (i & 15) * 4;
        int row = row0 + rl;
        const float* src;
        if (LAYER == 0) {
            if (row < NU) src = ue + (size_t)row * 64;
            else if (row < NU + NI) src = ie + (size_t)(row - NU) * 64;
            else src = te + (size_t)(row - NU - NI) * 64;
        } else {
            src = g_embsB + (size_t)row * 64;
        }
        float4 v = *(const float4*)(src + c4);
        Xs[xswz(c4 + 0, rl)] = v.x;
        Xs[xswz(c4 + 1, rl)] = v.y;
        Xs[xswz(c4 + 2, rl)] = v.z;
        Xs[xswz(c4 + 3, rl)] = v.w;
    }
    __syncthreads();

    const int tx = tid & 7, ty = tid >> 3;
    const int j0 = tx * 8, r0 = ty * 8;

    u64 acc[4][8];
    {
        float4 ba = *(const float4*)(b1 + j0);
        float4 bb = *(const float4*)(b1 + j0 + 4);
        u64 d0 = dup2(ba.x), d1 = dup2(ba.y), d2 = dup2(ba.z), d3 = dup2(ba.w);
        u64 d4 = dup2(bb.x), d5 = dup2(bb.y), d6 = dup2(bb.z), d7 = dup2(bb.w);
#pragma unroll
        for (int i = 0; i < 4; i++) {
            acc[i][0] = d0; acc[i][1] = d1; acc[i][2] = d2; acc[i][3] = d3;
            acc[i][4] = d4; acc[i][5] = d5; acc[i][6] = d6; acc[i][7] = d7;
        }
    }

#pragma unroll 8
    for (int k = 0; k < 64; k++) {
        int xb = k * 128 + (r0 ^ ((k >> 3 & 3) << 3));
        ulonglong2 xA = *(const ulonglong2*)&Xs[xb];
        ulonglong2 xB = *(const ulonglong2*)&Xs[xb + 4];
        float4 wa = *(const float4*)&Ws[k * 64 + tx * 4];
        float4 wb = *(const float4*)&Ws[k * 64 + 32 + tx * 4];
        u64 w0 = dup2(wa.x), w1 = dup2(wa.y), w2 = dup2(wa.z), w3 = dup2(wa.w);
        u64 w4 = dup2(wb.x), w5 = dup2(wb.y), w6 = dup2(wb.z), w7 = dup2(wb.w);
        acc[0][0] = ffma2(xA.x, w0, acc[0][0]); acc[0][1] = ffma2(xA.x, w1, acc[0][1]);
        acc[0][2] = ffma2(xA.x, w2, acc[0][2]); acc[0][3] = ffma2(xA.x, w3, acc[0][3]);
        acc[0][4] = ffma2(xA.x, w4, acc[0][4]); acc[0][5] = ffma2(xA.x, w5, acc[0][5]);
        acc[0][6] = ffma2(xA.x, w6, acc[0][6]); acc[0][7] = ffma2(xA.x, w7, acc[0][7]);
        acc[1][0] = ffma2(xA.y, w0, acc[1][0]); acc[1][1] = ffma2(xA.y, w1, acc[1][1]);
        acc[1][2] = ffma2(xA.y, w2, acc[1][2]); acc[1][3] = ffma2(xA.y, w3, acc[1][3]);
        acc[1][4] = ffma2(xA.y, w4, acc[1][4]); acc[1][5] = ffma2(xA.y, w5, acc[1][5]);
        acc[1][6] = ffma2(xA.y, w6, acc[1][6]); acc[1][7] = ffma2(xA.y, w7, acc[1][7]);
        acc[2][0] = ffma2(xB.x, w0, acc[2][0]); acc[2][1] = ffma2(xB.x, w1, acc[2][1]);
        acc[2][2] = ffma2(xB.x, w2, acc[2][2]); acc[2][3] = ffma2(xB.x, w3, acc[2][3]);
        acc[2][4] = ffma2(xB.x, w4, acc[2][4]); acc[2][5] = ffma2(xB.x, w5, acc[2][5]);
        acc[2][6] = ffma2(xB.x, w6, acc[2][6]); acc[2][7] = ffma2(xB.x, w7, acc[2][7]);
        acc[3][0] = ffma2(xB.y, w0, acc[3][0]); acc[3][1] = ffma2(xB.y, w1, acc[3][1]);
        acc[3][2] = ffma2(xB.y, w2, acc[3][2]); acc[3][3] = ffma2(xB.y, w3, acc[3][3]);
        acc[3][4] = ffma2(xB.y, w4, acc[3][4]); acc[3][5] = ffma2(xB.y, w5, acc[3][5]);
        acc[3][6] = ffma2(xB.y, w6, acc[3][6]); acc[3][7] = ffma2(xB.y, w7, acc[3][7]);
    }
    __syncthreads();

    {
        int mj = (tx & 3) << 3;
#pragma unroll
        for (int c = 0; c < 8; c++) {
            int j = j0 + c;
            u64 h[4];
#pragma unroll
            for (int i = 0; i < 4; i++) {
                float2 p = unpack2(acc[i][c]);
                h[i] = pack2(fmaxf(p.x, 0.f), fmaxf(p.y, 0.f));
            }
            ulonglong2 hA; hA.x = h[0]; hA.y = h[1];
            ulonglong2 hB; hB.x = h[2]; hB.y = h[3];
            int base = j * 128 + (r0 ^ mj);
            *(ulonglong2*)&Xs[base] = hA;
            *(ulonglong2*)&Xs[base + 4] = hB;
        }
    }
    for (int i = tid; i < 4096; i += 128) {
        int j = i >> 6, k = i & 63;
        Ws[wpos(k, j)] = W2[i];
    }
    __syncthreads();

    {
        float4 ba = *(const float4*)(b2 + j0);
        float4 bb = *(const float4*)(b2 + j0 + 4);
        u64 d0 = dup2(ba.x), d1 = dup2(ba.y), d2 = dup2(ba.z), d3 = dup2(ba.w);
        u64 d4 = dup2(bb.x), d5 = dup2(bb.y), d6 = dup2(bb.z), d7 = dup2(bb.w);
#pragma unroll
        for (int i = 0; i < 4; i++) {
            acc[i][0] = d0; acc[i][1] = d1; acc[i][2] = d2; acc[i][3] = d3;
            acc[i][4] = d4; acc[i][5] = d5; acc[i][6] = d6; acc[i][7] = d7;
        }
    }

#pragma unroll 8
    for (int k = 0; k < 64; k++) {
        int xb = k * 128 + (r0 ^ ((k >> 3 & 3) << 3));
        ulonglong2 xA = *(const ulonglong2*)&Xs[xb];
        ulonglong2 xB = *(const ulonglong2*)&Xs[xb + 4];
        float4 wa = *(const float4*)&Ws[k * 64 + tx * 4];
        float4 wb = *(const float4*)&Ws[k * 64 + 32 + tx * 4];
        u64 w0 = dup2(wa.x), w1 = dup2(wa.y), w2 = dup2(wa.z), w3 = dup2(wa.w);
        u64 w4 = dup2(wb.x), w5 = dup2(wb.y), w6 = dup2(wb.z), w7 = dup2(wb.w);
        acc[0][0] = ffma2(xA.x, w0, acc[0][0]); acc[0][1] = ffma2(xA.x, w1, acc[0][1]);
        acc[0][2] = ffma2(xA.x, w2, acc[0][2]); acc[0][3] = ffma2(xA.x, w3, acc[0][3]);
        acc[0][4] = ffma2(xA.x, w4, acc[0][4]); acc[0][5] = ffma2(xA.x, w5, acc[0][5]);
        acc[0][6] = ffma2(xA.x, w6, acc[0][6]); acc[0][7] = ffma2(xA.x, w7, acc[0][7]);
        acc[1][0] = ffma2(xA.y, w0, acc[1][0]); acc[1][1] = ffma2(xA.y, w1, acc[1][1]);
        acc[1][2] = ffma2(xA.y, w2, acc[1][2]); acc[1][3] = ffma2(xA.y, w3, acc[1][3]);
        acc[1][4] = ffma2(xA.y, w4, acc[1][4]); acc[1][5] = ffma2(xA.y, w5, acc[1][5]);
        acc[1][6] = ffma2(xA.y, w6, acc[1][6]); acc[1][7] = ffma2(xA.y, w7, acc[1][7]);
        acc[2][0] = ffma2(xB.x, w0, acc[2][0]); acc[2][1] = ffma2(xB.x, w1, acc[2][1]);
        acc[2][2] = ffma2(xB.x, w2, acc[2][2]); acc[2][3] = ffma2(xB.x, w3, acc[2][3]);
        acc[2][4] = ffma2(xB.x, w4, acc[2][4]); acc[2][5] = ffma2(xB.x, w5, acc[2][5]);
        acc[2][6] = ffma2(xB.x, w6, acc[2][6]); acc[2][7] = ffma2(xB.x, w7, acc[2][7]);
        acc[3][0] = ffma2(xB.y, w0, acc[3][0]); acc[3][1] = ffma2(xB.y, w1, acc[3][1]);
        acc[3][2] = ffma2(xB.y, w2, acc[3][2]); acc[3][3] = ffma2(xB.y, w3, acc[3][3]);
        acc[3][4] = ffma2(xB.y, w4, acc[3][4]); acc[3][5] = ffma2(xB.y, w5, acc[3][5]);
        acc[3][6] = ffma2(xB.y, w6, acc[3][6]); acc[3][7] = ffma2(xB.y, w7, acc[3][7]);
    }

    // epilogue: eh = exp(y), px = eh * x -> fp16 interleaved records
#pragma unroll
    for (int i = 0; i < 4; i++) {
        float2 u[8];
#pragma unroll
        for (int c = 0; c < 8; c++) u[c] = unpack2(acc[i][c]);
#pragma unroll
        for (int half = 0; half < 2; half++) {
            int row = row0 + r0 + 2 * i + half;
            const float* src;
            if (LAYER == 0) {
                if (row < NU) src = ue + (size_t)row * 64;
                else if (row < NU + NI) src = ie + (size_t)(row - NU) * 64;
                else src = te + (size_t)(row - NU - NI) * 64;
            } else {
                src = g_embsB + (size_t)row * 64;
            }
            float4 xa = *(const float4*)(src + j0);
            float4 xb = *(const float4*)(src + j0 + 4);
            float y0 = half ? u[0].y : u[0].x;
            float y1 = half ? u[1].y : u[1].x;
            float y2 = half ? u[2].y : u[2].x;
            float y3 = half ? u[3].y : u[3].x;
            float y4 = half ? u[4].y : u[4].x;
            float y5 = half ? u[5].y : u[5].x;
            float y6 = half ? u[6].y : u[6].x;
            float y7 = half ? u[7].y : u[7].x;
            float e0 = __expf(y0), e1 = __expf(y1), e2 = __expf(y2), e3 = __expf(y3);
            float e4 = __expf(y4), e5 = __expf(y5), e6 = __expf(y6), e7 = __expf(y7);
            size_t baseh = (size_t)row * 128 + (size_t)(2 * j0);  // halfs
            uint4 qa, qb;
            qa.x = h2bits(e0, e1);               qa.y = h2bits(e2, e3);
            qa.z = h2bits(e0 * xa.x, e1 * xa.y); qa.w = h2bits(e2 * xa.z, e3 * xa.w);
            qb.x = h2bits(e4, e5);               qb.y = h2bits(e6, e7);
            qb.z = h2bits(e4 * xb.x, e5 * xb.y); qb.w = h2bits(e6 * xb.z, e7 * xb.w);
            *(uint4*)&g_EPh[baseh]     = qa;
            *(uint4*)&g_EPh[baseh + 8] = qb;
        }
    }
}

// ---------------- per-node aggregation: fp16 EP single-load edge body ----------------
template <int FINAL>
__global__ __launch_bounds__(256) void aggregate_kernel(
    const float* __restrict__ uo, const float* __restrict__ io, const float* __restrict__ to,
    float* __restrict__ out) {
    int w = (blockIdx.x * blockDim.x + threadIdx.x) >> 5;
    if (w >= NNODES) return;
    int lane = threadIdx.x & 31;
    int half = lane >> 4;
    int li = lane & 15;
    int fl = li * 4;

    int beg = g_csr_off[w];
    int end = g_csr_off[w + 1];
    const bool is_user = (w < NU);
    const bool is_item = (w >= NU) && (w < NU + NI);

    float4 s = make_float4(0.f, 0.f, 0.f, 0.f);
    float4 n = make_float4(0.f, 0.f, 0.f, 0.f);
    float4 mn = make_float4(INFINITY, INFINITY, INFINITY, INFINITY);
    float4 mx = make_float4(0.f, 0.f, 0.f, 0.f);

    for (int chunk = beg; chunk < end; chunk += 32) {
        int nn = end - chunk; if (nn > 32) nn = 32;
        int tl = 0;
        if (lane < nn) tl = __ldg(&g_csr_tail[chunk + lane]);
#pragma unroll 4
        for (int q = 0; q < nn; q += 2) {
            int idx = q + half;
            int t = __shfl_sync(0xffffffffu, tl, idx & 31);
            if (idx < nn) {
                // one LDG.128: {eh x4 fp16, px x4 fp16}
                uint4 r = __ldg((const uint4*)&g_EPh[(size_t)t * 128 + (size_t)li * 8]);
                float2 e01 = h2f2(r.x), e23 = h2f2(r.y);
                float2 p01 = h2f2(r.z), p23 = h2f2(r.w);
                s.x += e01.x; s.y += e01.y; s.z += e23.x; s.w += e23.y;
                n.x += p01.x; n.y += p01.y; n.z += p23.x; n.w += p23.y;

                bool need_off = !(is_user && t < NU);
                if (need_off) {
                    const float* op;
                    if (FINAL == 0) {
                        if (t < NU)           op = uo + (size_t)t * 64;
                        else if (t < NU + NI) op = io + (size_t)(t - NU) * 64;
                        else                  op = to + (size_t)(t - NU - NI) * 64;
                    } else {
                        op = g_offB + (size_t)t * 64;
                    }
                    float4 o = __ldg((const float4*)(op + fl));
                    if (FINAL == 0) {
                        o.x = fmaxf(o.x, 0.f); o.y = fmaxf(o.y, 0.f);
                        o.z = fmaxf(o.z, 0.f); o.w = fmaxf(o.w, 0.f);
                    }
                    bool t_item = (t >= NU) && (t < NU + NI);
                    bool t_tag  = (t >= NU + NI);
                    bool do_min = is_user ? t_item : (!is_item);
                    bool do_max = is_user ? t_tag  : is_item;
                    if (do_min) {
                        mn.x = fminf(mn.x, o.x); mn.y = fminf(mn.y, o.y);
                        mn.z = fminf(mn.z, o.z); mn.w = fminf(mn.w, o.w);
                    }
                    if (do_max) {
                        mx.x = fmaxf(mx.x, o.x); mx.y = fmaxf(mx.y, o.y);
                        mx.z = fmaxf(mx.z, o.z); mx.w = fmaxf(mx.w, o.w);
                    }
                }
            }
        }
    }

#define MRG_ADD(v) v += __shfl_xor_sync(0xffffffffu, v, 16)
#define MRG_MIN(v) v = fminf(v, __shfl_xor_sync(0xffffffffu, v, 16))
#define MRG_MAX(v) v = fmaxf(v, __shfl_xor_sync(0xffffffffu, v, 16))
    MRG_ADD(s.x); MRG_ADD(s.y); MRG_ADD(s.z); MRG_ADD(s.w);
    MRG_ADD(n.x); MRG_ADD(n.y); MRG_ADD(n.z); MRG_ADD(n.w);
    MRG_MIN(mn.x); MRG_MIN(mn.y); MRG_MIN(mn.z); MRG_MIN(mn.w);
    MRG_MAX(mx.x); MRG_MAX(mx.y); MRG_MAX(mx.z); MRG_MAX(mx.w);

    float4 a;
    a.x = (s.x > 0.f) ? __fdividef(n.x, s.x) : 0.f;
    a.y = (s.y > 0.f) ? __fdividef(n.y, s.y) : 0.f;
    a.z = (s.z > 0.f) ? __fdividef(n.z, s.z) : 0.f;
    a.w = (s.w > 0.f) ? __fdividef(n.w, s.w) : 0.f;

    float ss = a.x * a.x + a.y * a.y + a.z * a.z + a.w * a.w;
#pragma unroll
    for (int of = 8; of; of >>= 1) ss += __shfl_xor_sync(0xffffffffu, ss, of);
    float inv = rcp_approx(fmaxf(sqrt_approx(ss), 1e-12f));
    a.x *= inv; a.y *= inv; a.z *= inv; a.w *= inv;

    float4 ov;
    if (is_user) {
        float i0 = isinf(mn.x) ? 0.f : mn.x;
        float i1 = isinf(mn.y) ? 0.f : mn.y;
        float i2 = isinf(mn.z) ? 0.f : mn.z;
        float i3 = isinf(mn.w) ? 0.f : mn.w;
        ov = make_float4(fminf(i0, mx.x), fminf(i1, mx.y), fminf(i2, mx.z), fminf(i3, mx.w));
    } else if (is_item) {
        ov = mx;
    } else {
        ov.x = isinf(mn.x) ? 0.f : mn.x;
        ov.y = isinf(mn.y) ? 0.f : mn.y;
        ov.z = isinf(mn.z) ? 0.f : mn.z;
        ov.w = isinf(mn.w) ? 0.f : mn.w;
    }
    ov.x = fmaxf(ov.x, 0.f); ov.y = fmaxf(ov.y, 0.f);
    ov.z = fmaxf(ov.z, 0.f); ov.w = fmaxf(ov.w, 0.f);

    if (FINAL == 0) {
        size_t base = (size_t)w * 64 + fl;
        if (half == 0) *(float4*)(g_embsB + base) = a;
        else           *(float4*)(g_offB + base)  = ov;
    } else {
        size_t eb, ob;
        if (is_user) {
            eb = (size_t)w * 64;
            ob = (size_t)NU * 64 + (size_t)w * 64;
        } else if (is_item) {
            size_t b2 = (size_t)2 * NU * 64;
            eb = b2 + (size_t)(w - NU) * 64;
            ob = b2 + (size_t)NI * 64 + (size_t)(w - NU) * 64;
        } else {
            size_t b3 = (size_t)2 * (NU + NI) * 64;
            eb = b3 + (size_t)(w - NU - NI) * 64;
            ob = b3 + (size_t)NT * 64 + (size_t)(w - NU - NI) * 64;
        }
        if (half == 0) *(float4*)(out + eb + fl) = a;
        else           *(float4*)(out + ob + fl) = ov;
    }
}

// ---------------- launch ----------------
extern "C" void kernel_launch(void* const* d_in, const int* in_sizes, int n_in,
                              void* d_out, int out_size) {
    const float* user_emb = (const float*)d_in[0];
    const float* user_off = (const float*)d_in[1];
    const float* item_emb = (const float*)d_in[2];
    const float* item_off = (const float*)d_in[3];
    const float* tag_emb  = (const float*)d_in[4];
    const float* tag_off  = (const float*)d_in[5];
    const float* W1 = (const float*)d_in[6];
    const float* b1 = (const float*)d_in[7];
    const float* W2 = (const float*)d_in[8];
    const float* b2 = (const float*)d_in[9];
    const int* head = (const int*)d_in[10];
    const int* tail = (const int*)d_in[11];
    float* out = (float*)d_out;

    const int NB = (NNODES + SCAN_B - 1) / SCAN_B;

    // slot #4 (ncu capture) = mlp<0> (control); CSR chain completes before aggregate<0>
    zero_deg_kernel<<<(NNODES + 255) / 256, 256>>>(); // 1
    hist_kernel<<<(NE + 255) / 256, 256>>>(head);     // 2
    scan_block_kernel<<<NB, SCAN_B>>>();              // 3
    mlp_kernel<0><<<NNODES / 128, 128>>>(user_emb, item_emb, tag_emb,
                                         W1, b1, W2, b2);  // 4 <- profiled
    scan_sums_kernel<<<1, 256>>>(NB);                 // 5
    scan_add_kernel<<<NB, SCAN_B>>>();                // 6
    scatter_kernel<<<(NE + 255) / 256, 256>>>(head, tail);  // 7
    aggregate_kernel<0><<<(NNODES + 7) / 8, 256>>>(
        user_off, item_off, tag_off, out);            // 8
    mlp_kernel<1><<<NNODES / 128, 128>>>(user_emb, item_emb, tag_emb,
                                         W1, b1, W2, b2);   // 9
    aggregate_kernel<1><<<(NNODES + 7) / 8, 256>>>(
        user_off, item_off, tag_off, out);            // 10
}